// round 10
// baseline (speedup 1.0000x reference)
#include <cuda_runtime.h>
#include <cuda_bf16.h>
#include <cstdint>

#define DIM   256
#define NCLS  20
#define MAXN  50000
#define MAXE  800000
#define BN_EPS 1e-5f
#define KPAD0 1024

// ==================== device scratch =======================================
__device__ int   g_cnt[MAXN];
__device__ int   g_rowptr[MAXN + 1];
__device__ int   g_cursor[MAXN];
__device__ int   g_adj[MAXE];
__device__ float g_dinv[MAXN];
__device__ float g_bnsum[2 * DIM];
__device__ int   g_is64;
// activation planes (hi/lo bf16 as u16) — same bytes as fp32, cp.async-ready
__device__ unsigned short g_xh[(size_t)MAXN * KPAD0];
__device__ unsigned short g_xl[(size_t)MAXN * KPAD0];
__device__ unsigned short g_pAh[(size_t)MAXN * DIM];
__device__ unsigned short g_pAl[(size_t)MAXN * DIM];
__device__ unsigned short g_pBh[(size_t)MAXN * DIM];
__device__ unsigned short g_pBl[(size_t)MAXN * DIM];
// weight splits: [N=256][Kpad]; lin (Kpad=1024) + 3 x (Kpad=256)
#define WOFF0 0
#define WOFF1 (256 * 1024)
#define WOFF2 (WOFF1 + 256 * 256)
#define WOFF3 (WOFF2 + 256 * 256)
#define WTOT  (WOFF3 + 256 * 256)
__device__ unsigned short g_whi[WTOT];
__device__ unsigned short g_wlo[WTOT];

// ==================== PTX helpers (non-'a' only!) ==========================
__device__ __forceinline__ uint32_t smem_u32(const void* p) {
    uint32_t a;
    asm("{ .reg .u64 t; cvta.to.shared.u64 t, %1; cvt.u32.u64 %0, t; }" : "=r"(a) : "l"(p));
    return a;
}
#define LDSM_X4(r, addr) \
    asm volatile("ldmatrix.sync.aligned.m8n8.x4.shared.b16 {%0,%1,%2,%3}, [%4];" \
        : "=r"((r)[0]), "=r"((r)[1]), "=r"((r)[2]), "=r"((r)[3]) : "r"(addr))
#define MMA_BF16(cv, a, b0v, b1v) \
    asm volatile("mma.sync.aligned.m16n8k16.row.col.f32.bf16.bf16.f32 " \
        "{%0,%1,%2,%3}, {%4,%5,%6,%7}, {%8,%9}, {%0,%1,%2,%3};" \
        : "+f"((cv)[0]), "+f"((cv)[1]), "+f"((cv)[2]), "+f"((cv)[3]) \
        : "r"((a)[0]), "r"((a)[1]), "r"((a)[2]), "r"((a)[3]), "r"(b0v), "r"(b1v))
#define CP_ASYNC16(dst, src) \
    asm volatile("cp.async.ca.shared.global [%0], [%1], 16;" :: "r"(dst), "l"(src))
#define CP_COMMIT() asm volatile("cp.async.commit_group;" ::: "memory")

// split a pair of f32 into packed hi (bf16 truncation) + lo (bf16 residual)
__device__ __forceinline__ void split2(float v0, float v1, unsigned& hp, unsigned& lp) {
    unsigned u0 = __float_as_uint(v0), u1 = __float_as_uint(v1);
    hp = __byte_perm(u0, u1, 0x7632);
    float l0 = v0 - __uint_as_float(u0 & 0xFFFF0000u);
    float l1 = v1 - __uint_as_float(u1 & 0xFFFF0000u);
    __nv_bfloat162 lb = __floats2bfloat162_rn(l0, l1);
    lp = *(unsigned*)&lb;
}
// reconstruct pair of f32 from packed planes
__device__ __forceinline__ float2 recon2(unsigned h, unsigned l) {
    float2 lf = __bfloat1622float2(*(__nv_bfloat162*)&l);
    float2 r;
    r.x = __uint_as_float(h << 16) + lf.x;
    r.y = __uint_as_float(h & 0xFFFF0000u) + lf.y;
    return r;
}

// ==================== x split: fp32 [M][K] -> planes [M][1024] =============
__global__ void k_xsplit(const float* __restrict__ x, int M, int K,
                         unsigned short* __restrict__ xh, unsigned short* __restrict__ xl)
{
    long long i = (long long)blockIdx.x * blockDim.x + threadIdx.x;
    long long total = (long long)M * (KPAD0 / 2);
    if (i >= total) return;
    int row = (int)(i >> 9);
    int p   = (int)(i & 511);
    float2 v = make_float2(0.f, 0.f);
    if (2 * p + 1 < K) v = *(const float2*)(x + (size_t)row * K + 2 * p);
    else if (2 * p < K) v.x = x[(size_t)row * K + 2 * p];
    unsigned hp, lp;
    split2(v.x, v.y, hp, lp);
    ((unsigned*)xh)[(size_t)row * 512 + p] = hp;
    ((unsigned*)xl)[(size_t)row * 512 + p] = lp;
}

// ==================== init / CSR build =====================================
__global__ void k_init(const void* eiv, int E, int n) {
    int i = blockIdx.x * blockDim.x + threadIdx.x;
    if (i < n) g_cnt[i] = 0;
    if (i < 2 * DIM) g_bnsum[i] = 0.f;
    if (i == 0) {
        const long long* p = (const long long*)eiv;
        int ok = 1;
        int m = E < 64 ? E : 64;
        for (int k = 0; k < m; k++) {
            long long v = p[k];
            if (v < 0 || v >= (long long)n) { ok = 0; break; }
        }
        g_is64 = ok;
    }
}
__global__ void k_count(const void* eiv, int E) {
    int e = blockIdx.x * blockDim.x + threadIdx.x;
    if (e >= E) return;
    int d;
    if (g_is64) d = (int)((const long long*)eiv)[(size_t)E + e];
    else        d = ((const int*)eiv)[(size_t)E + e];
    atomicAdd(&g_cnt[d], 1);
}
__global__ void k_scan(int n) {
    __shared__ int part[1024];
    int t = threadIdx.x;
    int chunk = (n + 1023) >> 10;
    int beg = t * chunk;
    int end = beg + chunk; if (end > n) end = n;
    int s = 0;
    for (int i = beg; i < end; i++) s += g_cnt[i];
    part[t] = s;
    __syncthreads();
    for (int off = 1; off < 1024; off <<= 1) {
        int v = 0;
        if (t >= off) v = part[t - off];
        __syncthreads();
        part[t] += v;
        __syncthreads();
    }
    int run = (t == 0) ? 0 : part[t - 1];
    for (int i = beg; i < end; i++) {
        int c = g_cnt[i];
        g_rowptr[i] = run;
        g_cursor[i] = run;
        g_dinv[i] = rsqrtf((float)c + 1.0f);
        run += c;
    }
    if (beg < n && end == n) g_rowptr[n] = run;
}
__global__ void k_fill(const void* eiv, int E) {
    int e = blockIdx.x * blockDim.x + threadIdx.x;
    if (e >= E) return;
    int s, d;
    if (g_is64) {
        const long long* p = (const long long*)eiv;
        s = (int)p[e]; d = (int)p[(size_t)E + e];
    } else {
        const int* p = (const int*)eiv;
        s = p[e]; d = p[(size_t)E + e];
    }
    int pos = atomicAdd(&g_cursor[d], 1);
    g_adj[pos] = s;
}

// ==================== weight prep: tiled transpose + bf16 split ============
__global__ void k_wprep(const float* __restrict__ w, int K, int Kpad,
                        unsigned short* __restrict__ hi, unsigned short* __restrict__ lo)
{
    __shared__ float t[32][33];
    int k0 = blockIdx.x * 32, n0 = blockIdx.y * 32;
    int tx = threadIdx.x, ty = threadIdx.y;   // 32 x 8
#pragma unroll
    for (int r = 0; r < 4; r++) {
        int k = k0 + ty + r * 8;
        t[ty + r * 8][tx] = (k < K) ? w[(size_t)k * 256 + n0 + tx] : 0.f;
    }
    __syncthreads();
#pragma unroll
    for (int r = 0; r < 4; r++) {
        int nn = n0 + ty + r * 8;
        int k  = k0 + tx;
        float f = t[tx][ty + r * 8];
        unsigned u = __float_as_uint(f);
        unsigned short hp = (unsigned short)(u >> 16);
        float hf = __uint_as_float(u & 0xFFFF0000u);
        __nv_bfloat16 lb = __float2bfloat16(f - hf);
        hi[(size_t)nn * Kpad + k] = hp;
        lo[(size_t)nn * Kpad + k] = __bfloat16_as_ushort(lb);
    }
}

// ==================== plane GEMM: C = A @ W^T, all cp.async ================
// A planes [M][Kpad], B planes [256][Kpad]; C planes [M][256].
// CTA tile 128x128 (grid: (2, rowblocks)); 8 warps 4(M)x2(N); BK=32.
// 2-stage double buffer; zero register liveness across the MMA section.
#define SM_P 80
#define SM_A_H 0
#define SM_A_L 10240
#define SM_B_H 20480
#define SM_B_L 30720
#define STG_SZ 40960
__global__ __launch_bounds__(256, 2) void k_pgemm(
    const unsigned short* __restrict__ Ahi, const unsigned short* __restrict__ Alo,
    const unsigned short* __restrict__ Bhi, const unsigned short* __restrict__ Blo,
    const float* __restrict__ bias,
    unsigned short* __restrict__ Chi, unsigned short* __restrict__ Clo,
    int M, int Kpad)
{
    extern __shared__ __align__(16) unsigned char sm[];
    uint32_t sb = smem_u32(sm);
    int tid = threadIdx.x, wid = tid >> 5, lane = tid & 31;
    int row0 = blockIdx.y * 128;
    int c0   = blockIdx.x * 128;
    int wm = wid & 3, wn = wid >> 2;

    float cacc[2][8][4];
#pragma unroll
    for (int a = 0; a < 2; a++)
#pragma unroll
        for (int b = 0; b < 8; b++)
#pragma unroll
            for (int d = 0; d < 4; d++) cacc[a][b][d] = 0.f;

    // loader mapping: 2 threads per 128 rows; each does 2x16B per plane
    int arow = tid >> 1;
    int half = tid & 1;
    bool aOK = (row0 + arow) < M;
    const unsigned short* AhB = Ahi + (size_t)(row0 + arow) * Kpad + half * 16;
    const unsigned short* AlB = Alo + (size_t)(row0 + arow) * Kpad + half * 16;
    const unsigned short* BhB = Bhi + (size_t)(c0 + arow) * Kpad + half * 16;
    const unsigned short* BlB = Blo + (size_t)(c0 + arow) * Kpad + half * 16;
    uint32_t sOff = (uint32_t)(arow * SM_P + half * 32);

    // ldmatrix lane addresses (R5-proven layout)
    uint32_t aOff = (uint32_t)((wm * 32 + (lane & 15)) * SM_P + (lane >> 4) * 16);
    uint32_t bOff = (uint32_t)((wn * 64 + (lane & 7) + ((lane >> 4) & 1) * 8) * SM_P
                               + ((lane >> 3) & 1) * 16);

#define ISSUE_STAGE(stg_, kb_) do { \
    if (aOK) { \
        CP_ASYNC16((stg_) + SM_A_H + sOff,      AhB + (kb_)); \
        CP_ASYNC16((stg_) + SM_A_H + sOff + 16, AhB + (kb_) + 8); \
        CP_ASYNC16((stg_) + SM_A_L + sOff,      AlB + (kb_)); \
        CP_ASYNC16((stg_) + SM_A_L + sOff + 16, AlB + (kb_) + 8); \
    } \
    CP_ASYNC16((stg_) + SM_B_H + sOff,      BhB + (kb_)); \
    CP_ASYNC16((stg_) + SM_B_H + sOff + 16, BhB + (kb_) + 8); \
    CP_ASYNC16((stg_) + SM_B_L + sOff,      BlB + (kb_)); \
    CP_ASYNC16((stg_) + SM_B_L + sOff + 16, BlB + (kb_) + 8); \
} while (0)

    int NB = Kpad >> 5;
    // prologue: stage 0
    ISSUE_STAGE(sb, 0);
    CP_COMMIT();

    for (int ib = 0; ib < NB; ib++) {
        uint32_t cur = sb + (uint32_t)(ib & 1) * STG_SZ;
        if (ib + 1 < NB) {
            // next-stage buffer was consumed in iter ib-1 (barrier below protects)
            uint32_t nst = sb + (uint32_t)((ib + 1) & 1) * STG_SZ;
            int kb = (ib + 1) << 5;
            ISSUE_STAGE(nst, kb);
            CP_COMMIT();
            asm volatile("cp.async.wait_group 1;" ::: "memory");  // cur complete
        } else {
            asm volatile("cp.async.wait_group 0;" ::: "memory");
        }
        __syncthreads();   // cur visible to all warps

        // ---- compute: 2 k-frags x (4 n-pairs x 2 m-frags x 3 products)
#pragma unroll
        for (int kf = 0; kf < 2; kf++) {
            uint32_t ah[2][4], al[2][4];
#pragma unroll
            for (int mf = 0; mf < 2; mf++) {
                uint32_t addr = cur + aOff + (uint32_t)(mf * 16 * SM_P + kf * 32);
                LDSM_X4(ah[mf], addr + SM_A_H);
                LDSM_X4(al[mf], addr + SM_A_L);
            }
#pragma unroll
            for (int np = 0; np < 4; np++) {
                uint32_t bh[4], bl[4];
                uint32_t addr = cur + bOff + (uint32_t)(np * 16 * SM_P + kf * 32);
                LDSM_X4(bh, addr + SM_B_H);
                LDSM_X4(bl, addr + SM_B_L);
#pragma unroll
                for (int mf = 0; mf < 2; mf++) {
                    MMA_BF16(cacc[mf][np * 2],     ah[mf], bh[0], bh[1]);
                    MMA_BF16(cacc[mf][np * 2],     ah[mf], bl[0], bl[1]);
                    MMA_BF16(cacc[mf][np * 2],     al[mf], bh[0], bh[1]);
                    MMA_BF16(cacc[mf][np * 2 + 1], ah[mf], bh[2], bh[3]);
                    MMA_BF16(cacc[mf][np * 2 + 1], ah[mf], bl[2], bl[3]);
                    MMA_BF16(cacc[mf][np * 2 + 1], al[mf], bh[2], bh[3]);
                }
            }
        }
        __syncthreads();   // all warps done with cur before it is rewritten
    }
#undef ISSUE_STAGE

    // ---- epilogue: write output planes
    int g = lane >> 2, tq = lane & 3;
#pragma unroll
    for (int mf = 0; mf < 2; mf++) {
        int r = row0 + wm * 32 + mf * 16 + g;
#pragma unroll
        for (int nf = 0; nf < 8; nf++) {
            int cc = c0 + wn * 64 + nf * 8 + tq * 2;
            float b0 = 0.f, b1 = 0.f;
            if (bias) { b0 = __ldg(bias + cc); b1 = __ldg(bias + cc + 1); }
            float v0 = cacc[mf][nf][0] + b0, v1 = cacc[mf][nf][1] + b1;
            float v2 = cacc[mf][nf][2] + b0, v3 = cacc[mf][nf][3] + b1;
            unsigned hp, lp;
            if (r < M) {
                split2(v0, v1, hp, lp);
                *(unsigned*)(Chi + (size_t)r * 256 + cc) = hp;
                *(unsigned*)(Clo + (size_t)r * 256 + cc) = lp;
            }
            if (r + 8 < M) {
                split2(v2, v3, hp, lp);
                *(unsigned*)(Chi + (size_t)(r + 8) * 256 + cc) = hp;
                *(unsigned*)(Clo + (size_t)(r + 8) * 256 + cc) = lp;
            }
        }
    }
}

// ==================== GCN aggregation (warp per node, planes) ==============
__global__ void k_aggregate(const unsigned short* __restrict__ thi,
                            const unsigned short* __restrict__ tlo,
                            const float* __restrict__ bias,
                            unsigned short* __restrict__ ohi,
                            unsigned short* __restrict__ olo, int n)
{
    int warp = (blockIdx.x * blockDim.x + threadIdx.x) >> 5;
    int lane = threadIdx.x & 31;
    if (warp >= n) return;
    int node = warp;
    float dd  = g_dinv[node];
    int beg = g_rowptr[node], end = g_rowptr[node + 1];
    float acc[8];
#pragma unroll
    for (int j = 0; j < 8; j++) acc[j] = 0.f;
    for (int j = beg; j < end; j++) {
        int s = g_adj[j];
        float ds = g_dinv[s];
        uint4 hv = *((const uint4*)(thi + (size_t)s * DIM) + lane);
        uint4 lv = *((const uint4*)(tlo + (size_t)s * DIM) + lane);
        float2 p;
        p = recon2(hv.x, lv.x); acc[0] += ds * p.x; acc[1] += ds * p.y;
        p = recon2(hv.y, lv.y); acc[2] += ds * p.x; acc[3] += ds * p.y;
        p = recon2(hv.z, lv.z); acc[4] += ds * p.x; acc[5] += ds * p.y;
        p = recon2(hv.w, lv.w); acc[6] += ds * p.x; acc[7] += ds * p.y;
    }
    // self term + bias + relu
    uint4 shv = *((const uint4*)(thi + (size_t)node * DIM) + lane);
    uint4 slv = *((const uint4*)(tlo + (size_t)node * DIM) + lane);
    float4 b0 = ((const float4*)bias)[lane * 2];
    float4 b1 = ((const float4*)bias)[lane * 2 + 1];
    float dd2 = dd * dd;
    float v[8];
    float2 p;
    p = recon2(shv.x, slv.x); v[0] = dd * acc[0] + dd2 * p.x + b0.x; v[1] = dd * acc[1] + dd2 * p.y + b0.y;
    p = recon2(shv.y, slv.y); v[2] = dd * acc[2] + dd2 * p.x + b0.z; v[3] = dd * acc[3] + dd2 * p.y + b0.w;
    p = recon2(shv.z, slv.z); v[4] = dd * acc[4] + dd2 * p.x + b1.x; v[5] = dd * acc[5] + dd2 * p.y + b1.y;
    p = recon2(shv.w, slv.w); v[6] = dd * acc[6] + dd2 * p.x + b1.z; v[7] = dd * acc[7] + dd2 * p.y + b1.w;
#pragma unroll
    for (int j = 0; j < 8; j++) v[j] = fmaxf(v[j], 0.f);
    uint4 oh, ol;
    split2(v[0], v[1], oh.x, ol.x);
    split2(v[2], v[3], oh.y, ol.y);
    split2(v[4], v[5], oh.z, ol.z);
    split2(v[6], v[7], oh.w, ol.w);
    *((uint4*)(ohi + (size_t)node * DIM) + lane) = oh;
    *((uint4*)(olo + (size_t)node * DIM) + lane) = ol;
}

// ==================== BN stats + fused final (planes) ======================
__global__ void k_bnreduce(const unsigned short* __restrict__ thi,
                           const unsigned short* __restrict__ tlo, int n)
{
    int f = threadIdx.x;
    float s = 0.f, q = 0.f;
    for (int r = blockIdx.x; r < n; r += gridDim.x) {
        unsigned short h = thi[(size_t)r * DIM + f];
        unsigned short l = tlo[(size_t)r * DIM + f];
        float v = __uint_as_float(((unsigned)h) << 16) + __bfloat162float(*(__nv_bfloat16*)&l);
        s += v; q += v * v;
    }
    atomicAdd(&g_bnsum[f], s);
    atomicAdd(&g_bnsum[DIM + f], q);
}

__global__ __launch_bounds__(256) void k_final(
    const unsigned short* __restrict__ thi, const unsigned short* __restrict__ tlo,
    const float* __restrict__ w2, const float* __restrict__ b2,
    const float* __restrict__ gamma, const float* __restrict__ beta,
    float* __restrict__ out, int n)
{
    __shared__ float sW[DIM * NCLS];
    __shared__ float sA[DIM], sB[DIM];
    __shared__ float sb2[NCLS];
    __shared__ float sH[8][DIM];
    int tid = threadIdx.x;
    for (int i = tid; i < DIM * NCLS; i += 256) sW[i] = w2[i];
    if (tid < NCLS) sb2[tid] = b2[tid];
    {
        float invn = 1.0f / (float)n;
        float mu  = g_bnsum[tid] * invn;
        float var = g_bnsum[DIM + tid] * invn - mu * mu;
        float rs  = rsqrtf(var + BN_EPS);
        float a   = rs * gamma[tid];
        sA[tid] = a;
        sB[tid] = beta[tid] - mu * a;
    }
    __syncthreads();

    int warp = tid >> 5, lane = tid & 31;
    int node = blockIdx.x * 8 + warp;
    if (node >= n) return;

    uint4 hv = *((const uint4*)(thi + (size_t)node * DIM) + lane);
    uint4 lv = *((const uint4*)(tlo + (size_t)node * DIM) + lane);
    int f0 = lane * 8;
    {
        float2 p;
        p = recon2(hv.x, lv.x);
        sH[warp][f0 + 0] = fmaxf(p.x * sA[f0 + 0] + sB[f0 + 0], 0.f);
        sH[warp][f0 + 1] = fmaxf(p.y * sA[f0 + 1] + sB[f0 + 1], 0.f);
        p = recon2(hv.y, lv.y);
        sH[warp][f0 + 2] = fmaxf(p.x * sA[f0 + 2] + sB[f0 + 2], 0.f);
        sH[warp][f0 + 3] = fmaxf(p.y * sA[f0 + 3] + sB[f0 + 3], 0.f);
        p = recon2(hv.z, lv.z);
        sH[warp][f0 + 4] = fmaxf(p.x * sA[f0 + 4] + sB[f0 + 4], 0.f);
        sH[warp][f0 + 5] = fmaxf(p.y * sA[f0 + 5] + sB[f0 + 5], 0.f);
        p = recon2(hv.w, lv.w);
        sH[warp][f0 + 6] = fmaxf(p.x * sA[f0 + 6] + sB[f0 + 6], 0.f);
        sH[warp][f0 + 7] = fmaxf(p.y * sA[f0 + 7] + sB[f0 + 7], 0.f);
    }
    __syncwarp();

    float logit = -1e30f;
    if (lane < NCLS) {
        float acc = sb2[lane];
#pragma unroll 8
        for (int f = 0; f < DIM; f++) acc += sH[warp][f] * sW[f * NCLS + lane];
        logit = acc;
    }
    float m = logit;
#pragma unroll
    for (int off = 16; off; off >>= 1) m = fmaxf(m, __shfl_xor_sync(0xffffffffu, m, off));
    float e = (lane < NCLS) ? __expf(logit - m) : 0.f;
    float ssum = e;
#pragma unroll
    for (int off = 16; off; off >>= 1) ssum += __shfl_xor_sync(0xffffffffu, ssum, off);
    if (lane < NCLS) out[(size_t)node * NCLS + lane] = e / ssum;
}

// ==================== host =================================================
extern "C" void kernel_launch(void* const* d_in, const int* in_sizes, int n_in,
                              void* d_out, int out_size)
{
    const float* x    = (const float*)d_in[0];
    const void*  ei   = d_in[1];
    const float* linw = (const float*)d_in[2];
    const float* c1w  = (const float*)d_in[3];
    const float* c1b  = (const float*)d_in[4];
    const float* c2w  = (const float*)d_in[5];
    const float* c2b  = (const float*)d_in[6];
    const float* m1w  = (const float*)d_in[7];
    const float* m1b  = (const float*)d_in[8];
    const float* gam  = (const float*)d_in[9];
    const float* bet  = (const float*)d_in[10];
    const float* m2w  = (const float*)d_in[11];
    const float* m2b  = (const float*)d_in[12];
    float* out = (float*)d_out;

    int Dd = in_sizes[4];                 // 256
    int G  = in_sizes[2] / Dd;            // 1002
    int n  = in_sizes[0] / G;             // 50000
    int E  = in_sizes[1] / 2;             // 800000

    unsigned short *xh, *xl, *pAh, *pAl, *pBh, *pBl, *whi, *wlo;
    cudaGetSymbolAddress((void**)&xh,  g_xh);
    cudaGetSymbolAddress((void**)&xl,  g_xl);
    cudaGetSymbolAddress((void**)&pAh, g_pAh);
    cudaGetSymbolAddress((void**)&pAl, g_pAl);
    cudaGetSymbolAddress((void**)&pBh, g_pBh);
    cudaGetSymbolAddress((void**)&pBl, g_pBl);
    cudaGetSymbolAddress((void**)&whi, g_whi);
    cudaGetSymbolAddress((void**)&wlo, g_wlo);

    const int GEMM_SMEM = 2 * STG_SZ;   // 81920
    cudaFuncSetAttribute(k_pgemm, cudaFuncAttributeMaxDynamicSharedMemorySize, GEMM_SMEM);

    const int tpb = 256;
    dim3 wblk(32, 8);
    dim3 grd(2, (n + 127) / 128);
    long long xtot = (long long)n * (KPAD0 / 2);

    // ordered so GEMM1 lands in the ncu-profiled launch slot
    k_xsplit<<<(int)((xtot + tpb - 1) / tpb), tpb>>>(x, n, G, xh, xl);
    k_wprep<<<dim3(KPAD0 / 32, 8), wblk>>>(linw, G,   KPAD0, whi + WOFF0, wlo + WOFF0);
    k_wprep<<<dim3(8, 8),          wblk>>>(c1w,  256, 256,   whi + WOFF1, wlo + WOFF1);
    k_pgemm<<<grd, 256, GEMM_SMEM>>>(xh, xl, whi + WOFF0, wlo + WOFF0, nullptr, pAh, pAl, n, KPAD0);
    k_wprep<<<dim3(8, 8),          wblk>>>(c2w,  256, 256,   whi + WOFF2, wlo + WOFF2);
    k_wprep<<<dim3(8, 8),          wblk>>>(m1w,  256, 256,   whi + WOFF3, wlo + WOFF3);

    int initN = (n > 2 * DIM) ? n : 2 * DIM;
    k_init<<<(initN + tpb - 1) / tpb, tpb>>>(ei, E, n);
    k_count<<<(E + tpb - 1) / tpb, tpb>>>(ei, E);
    k_scan<<<1, 1024>>>(n);
    k_fill<<<(E + tpb - 1) / tpb, tpb>>>(ei, E);

    k_pgemm<<<grd, 256, GEMM_SMEM>>>(pAh, pAl, whi + WOFF1, wlo + WOFF1, nullptr, pBh, pBl, n, 256);
    k_aggregate<<<(n + 7) / 8, 256>>>(pBh, pBl, c1b, pAh, pAl, n);
    k_pgemm<<<grd, 256, GEMM_SMEM>>>(pAh, pAl, whi + WOFF2, wlo + WOFF2, nullptr, pBh, pBl, n, 256);
    k_aggregate<<<(n + 7) / 8, 256>>>(pBh, pBl, c2b, pAh, pAl, n);
    k_pgemm<<<grd, 256, GEMM_SMEM>>>(pAh, pAl, whi + WOFF3, wlo + WOFF3, m1b, pBh, pBl, n, 256);
    k_bnreduce<<<256, DIM>>>(pBh, pBl, n);
    k_final<<<(n + 7) / 8, 256>>>(pBh, pBl, m2w, m2b, gam, bet, out, n);
}

// round 11
// speedup vs baseline: 1.1285x; 1.1285x over previous
#include <cuda_runtime.h>
#include <cuda_fp16.h>
#include <cstdint>

#define DIM   256
#define NCLS  20
#define MAXN  50000
#define MAXE  800000
#define BN_EPS 1e-5f
#define KPAD0 1024

// ==================== device scratch =======================================
__device__ int   g_cnt[MAXN];
__device__ int   g_rowptr[MAXN + 1];
__device__ int   g_cursor[MAXN];
__device__ int   g_adj[MAXE];
__device__ float g_dinv[MAXN];
__device__ float g_bnsum[2 * DIM];
__device__ int   g_is64;
// activation planes (hi/lo fp16 as u16) — A side of every GEMM
__device__ unsigned short g_xh[(size_t)MAXN * KPAD0];
__device__ unsigned short g_xl[(size_t)MAXN * KPAD0];
__device__ unsigned short g_pAh[(size_t)MAXN * DIM];
__device__ unsigned short g_pAl[(size_t)MAXN * DIM];
__device__ unsigned short g_pBh[(size_t)MAXN * DIM];
__device__ unsigned short g_pBl[(size_t)MAXN * DIM];
// weights: SINGLE fp16 plane [N=256][Kpad]; lin (Kpad=1024) + 3 x (Kpad=256)
#define WOFF0 0
#define WOFF1 (256 * 1024)
#define WOFF2 (WOFF1 + 256 * 256)
#define WOFF3 (WOFF2 + 256 * 256)
#define WTOT  (WOFF3 + 256 * 256)
__device__ unsigned short g_whi[WTOT];

// ==================== PTX helpers (non-'a' only!) ==========================
__device__ __forceinline__ uint32_t smem_u32(const void* p) {
    uint32_t a;
    asm("{ .reg .u64 t; cvta.to.shared.u64 t, %1; cvt.u32.u64 %0, t; }" : "=r"(a) : "l"(p));
    return a;
}
#define LDSM_X4(r, addr) \
    asm volatile("ldmatrix.sync.aligned.m8n8.x4.shared.b16 {%0,%1,%2,%3}, [%4];" \
        : "=r"((r)[0]), "=r"((r)[1]), "=r"((r)[2]), "=r"((r)[3]) : "r"(addr))
#define MMA_F16(cv, a, b0v, b1v) \
    asm volatile("mma.sync.aligned.m16n8k16.row.col.f32.f16.f16.f32 " \
        "{%0,%1,%2,%3}, {%4,%5,%6,%7}, {%8,%9}, {%0,%1,%2,%3};" \
        : "+f"((cv)[0]), "+f"((cv)[1]), "+f"((cv)[2]), "+f"((cv)[3]) \
        : "r"((a)[0]), "r"((a)[1]), "r"((a)[2]), "r"((a)[3]), "r"(b0v), "r"(b1v))
#define CP_ASYNC16(dst, src) \
    asm volatile("cp.async.cg.shared.global [%0], [%1], 16;" :: "r"(dst), "l"(src))
#define CP_COMMIT() asm volatile("cp.async.commit_group;" ::: "memory")

// split pair of f32 into packed fp16 hi (rn) + fp16 residual lo
__device__ __forceinline__ void split2(float v0, float v1, unsigned& hp, unsigned& lp) {
    __half h0 = __float2half_rn(v0), h1 = __float2half_rn(v1);
    float r0 = v0 - __half2float(h0), r1 = v1 - __half2float(h1);
    __half l0 = __float2half_rn(r0), l1 = __float2half_rn(r1);
    hp = ((unsigned)__half_as_ushort(h1) << 16) | __half_as_ushort(h0);
    lp = ((unsigned)__half_as_ushort(l1) << 16) | __half_as_ushort(l0);
}
__device__ __forceinline__ float2 recon2(unsigned h, unsigned l) {
    float2 hf = __half22float2(*(__half2*)&h);
    float2 lf = __half22float2(*(__half2*)&l);
    return make_float2(hf.x + lf.x, hf.y + lf.y);
}

// ==================== x split: fp32 [M][K] -> planes [M][1024] =============
__global__ void k_xsplit(const float* __restrict__ x, int M, int K,
                         unsigned short* __restrict__ xh, unsigned short* __restrict__ xl)
{
    long long i = (long long)blockIdx.x * blockDim.x + threadIdx.x;
    long long total = (long long)M * (KPAD0 / 2);
    if (i >= total) return;
    int row = (int)(i >> 9);
    int p   = (int)(i & 511);
    float2 v = make_float2(0.f, 0.f);
    if (2 * p + 1 < K) v = *(const float2*)(x + (size_t)row * K + 2 * p);
    else if (2 * p < K) v.x = x[(size_t)row * K + 2 * p];
    unsigned hp, lp;
    split2(v.x, v.y, hp, lp);
    ((unsigned*)xh)[(size_t)row * 512 + p] = hp;
    ((unsigned*)xl)[(size_t)row * 512 + p] = lp;
}

// ==================== init / CSR build =====================================
__global__ void k_init(const void* eiv, int E, int n) {
    int i = blockIdx.x * blockDim.x + threadIdx.x;
    if (i < n) g_cnt[i] = 0;
    if (i < 2 * DIM) g_bnsum[i] = 0.f;
    if (i == 0) {
        const long long* p = (const long long*)eiv;
        int ok = 1;
        int m = E < 64 ? E : 64;
        for (int k = 0; k < m; k++) {
            long long v = p[k];
            if (v < 0 || v >= (long long)n) { ok = 0; break; }
        }
        g_is64 = ok;
    }
}
__global__ void k_count(const void* eiv, int E) {
    int e = blockIdx.x * blockDim.x + threadIdx.x;
    if (e >= E) return;
    int d;
    if (g_is64) d = (int)((const long long*)eiv)[(size_t)E + e];
    else        d = ((const int*)eiv)[(size_t)E + e];
    atomicAdd(&g_cnt[d], 1);
}
__global__ void k_scan(int n) {
    __shared__ int part[1024];
    int t = threadIdx.x;
    int chunk = (n + 1023) >> 10;
    int beg = t * chunk;
    int end = beg + chunk; if (end > n) end = n;
    int s = 0;
    for (int i = beg; i < end; i++) s += g_cnt[i];
    part[t] = s;
    __syncthreads();
    for (int off = 1; off < 1024; off <<= 1) {
        int v = 0;
        if (t >= off) v = part[t - off];
        __syncthreads();
        part[t] += v;
        __syncthreads();
    }
    int run = (t == 0) ? 0 : part[t - 1];
    for (int i = beg; i < end; i++) {
        int c = g_cnt[i];
        g_rowptr[i] = run;
        g_cursor[i] = run;
        g_dinv[i] = rsqrtf((float)c + 1.0f);
        run += c;
    }
    if (beg < n && end == n) g_rowptr[n] = run;
}
__global__ void k_fill(const void* eiv, int E) {
    int e = blockIdx.x * blockDim.x + threadIdx.x;
    if (e >= E) return;
    int s, d;
    if (g_is64) {
        const long long* p = (const long long*)eiv;
        s = (int)p[e]; d = (int)p[(size_t)E + e];
    } else {
        const int* p = (const int*)eiv;
        s = p[e]; d = p[(size_t)E + e];
    }
    int pos = atomicAdd(&g_cursor[d], 1);
    g_adj[pos] = s;
}

// ==================== weight prep: transpose + single fp16 plane ===========
__global__ void k_wprep(const float* __restrict__ w, int K, int Kpad,
                        unsigned short* __restrict__ hi)
{
    __shared__ float t[32][33];
    int k0 = blockIdx.x * 32, n0 = blockIdx.y * 32;
    int tx = threadIdx.x, ty = threadIdx.y;   // 32 x 8
#pragma unroll
    for (int r = 0; r < 4; r++) {
        int k = k0 + ty + r * 8;
        t[ty + r * 8][tx] = (k < K) ? w[(size_t)k * 256 + n0 + tx] : 0.f;
    }
    __syncthreads();
#pragma unroll
    for (int r = 0; r < 4; r++) {
        int nn = n0 + ty + r * 8;
        int k  = k0 + tx;
        hi[(size_t)nn * Kpad + k] = __half_as_ushort(__float2half_rn(t[tx][ty + r * 8]));
    }
}

// ==================== plane GEMM: C = A @ W^T ==============================
// A planes fp16 hi/lo [M][Kpad]; B single fp16 plane [256][Kpad].
// 2 MMAs per fragment set: (Ah + Al) x Bh  (B fp16-rn, err ~2^-13 stat).
// CTA 128x128, 8 warps 4(M)x2(N), BK=32, 2-stage, ONE barrier per iter.
#define SM_P 80
#define SM_A_H 0
#define SM_A_L 10240
#define SM_B_H 20480
#define STG_SZ 30720
__global__ __launch_bounds__(256, 2) void k_pgemm(
    const unsigned short* __restrict__ Ahi, const unsigned short* __restrict__ Alo,
    const unsigned short* __restrict__ Bhi,
    const float* __restrict__ bias,
    unsigned short* __restrict__ Chi, unsigned short* __restrict__ Clo,
    int M, int Kpad)
{
    extern __shared__ __align__(16) unsigned char sm[];
    uint32_t sb = smem_u32(sm);
    int tid = threadIdx.x, wid = tid >> 5, lane = tid & 31;
    int row0 = blockIdx.y * 128;
    int c0   = blockIdx.x * 128;
    int wm = wid & 3, wn = wid >> 2;

    float cacc[2][8][4];
#pragma unroll
    for (int a = 0; a < 2; a++)
#pragma unroll
        for (int b = 0; b < 8; b++)
#pragma unroll
            for (int d = 0; d < 4; d++) cacc[a][b][d] = 0.f;

    // loader mapping: 2 threads per row, 16 u16 (32B) each
    int arow = tid >> 1;
    int half = tid & 1;
    bool aOK = (row0 + arow) < M;
    const unsigned short* AhB = Ahi + (size_t)(row0 + arow) * Kpad + half * 16;
    const unsigned short* AlB = Alo + (size_t)(row0 + arow) * Kpad + half * 16;
    const unsigned short* BhB = Bhi + (size_t)(c0 + arow) * Kpad + half * 16;
    uint32_t sOff = (uint32_t)(arow * SM_P + half * 32);

    // ldmatrix lane addresses (R5-proven layout)
    uint32_t aOff = (uint32_t)((wm * 32 + (lane & 15)) * SM_P + (lane >> 4) * 16);
    uint32_t bOff = (uint32_t)((wn * 64 + (lane & 7) + ((lane >> 4) & 1) * 8) * SM_P
                               + ((lane >> 3) & 1) * 16);

#define ISSUE_STAGE(stg_, kb_) do { \
    if (aOK) { \
        CP_ASYNC16((stg_) + SM_A_H + sOff,      AhB + (kb_)); \
        CP_ASYNC16((stg_) + SM_A_H + sOff + 16, AhB + (kb_) + 8); \
        CP_ASYNC16((stg_) + SM_A_L + sOff,      AlB + (kb_)); \
        CP_ASYNC16((stg_) + SM_A_L + sOff + 16, AlB + (kb_) + 8); \
    } \
    CP_ASYNC16((stg_) + SM_B_H + sOff,      BhB + (kb_)); \
    CP_ASYNC16((stg_) + SM_B_H + sOff + 16, BhB + (kb_) + 8); \
} while (0)

    int NB = Kpad >> 5;
    ISSUE_STAGE(sb, 0);
    CP_COMMIT();

    for (int ib = 0; ib < NB; ib++) {
        uint32_t cur = sb + (uint32_t)(ib & 1) * STG_SZ;
        asm volatile("cp.async.wait_group 0;" ::: "memory");  // cur loads done
        __syncthreads();   // + everyone finished reading the other buffer
        if (ib + 1 < NB) {
            uint32_t nst = sb + (uint32_t)((ib + 1) & 1) * STG_SZ;
            ISSUE_STAGE(nst, (ib + 1) << 5);
            CP_COMMIT();   // overlaps the compute below
        }
        // ---- compute: 2 k-frags x (4 n-pairs x 2 m-frags x 2 products)
#pragma unroll
        for (int kf = 0; kf < 2; kf++) {
            uint32_t ah[2][4], al[2][4];
#pragma unroll
            for (int mf = 0; mf < 2; mf++) {
                uint32_t addr = cur + aOff + (uint32_t)(mf * 16 * SM_P + kf * 32);
                LDSM_X4(ah[mf], addr + SM_A_H);
                LDSM_X4(al[mf], addr + SM_A_L);
            }
#pragma unroll
            for (int np = 0; np < 4; np++) {
                uint32_t bh[4];
                uint32_t addr = cur + bOff + (uint32_t)(np * 16 * SM_P + kf * 32);
                LDSM_X4(bh, addr + SM_B_H);
#pragma unroll
                for (int mf = 0; mf < 2; mf++) {
                    MMA_F16(cacc[mf][np * 2],     ah[mf], bh[0], bh[1]);
                    MMA_F16(cacc[mf][np * 2],     al[mf], bh[0], bh[1]);
                    MMA_F16(cacc[mf][np * 2 + 1], ah[mf], bh[2], bh[3]);
                    MMA_F16(cacc[mf][np * 2 + 1], al[mf], bh[2], bh[3]);
                }
            }
        }
    }
#undef ISSUE_STAGE

    // ---- epilogue: write output planes
    int g = lane >> 2, tq = lane & 3;
#pragma unroll
    for (int mf = 0; mf < 2; mf++) {
        int r = row0 + wm * 32 + mf * 16 + g;
#pragma unroll
        for (int nf = 0; nf < 8; nf++) {
            int cc = c0 + wn * 64 + nf * 8 + tq * 2;
            float b0 = 0.f, b1 = 0.f;
            if (bias) { b0 = __ldg(bias + cc); b1 = __ldg(bias + cc + 1); }
            float v0 = cacc[mf][nf][0] + b0, v1 = cacc[mf][nf][1] + b1;
            float v2 = cacc[mf][nf][2] + b0, v3 = cacc[mf][nf][3] + b1;
            unsigned hp, lp;
            if (r < M) {
                split2(v0, v1, hp, lp);
                *(unsigned*)(Chi + (size_t)r * 256 + cc) = hp;
                *(unsigned*)(Clo + (size_t)r * 256 + cc) = lp;
            }
            if (r + 8 < M) {
                split2(v2, v3, hp, lp);
                *(unsigned*)(Chi + (size_t)(r + 8) * 256 + cc) = hp;
                *(unsigned*)(Clo + (size_t)(r + 8) * 256 + cc) = lp;
            }
        }
    }
}

// ==================== GCN aggregation (warp per node, planes) ==============
__global__ void k_aggregate(const unsigned short* __restrict__ thi,
                            const unsigned short* __restrict__ tlo,
                            const float* __restrict__ bias,
                            unsigned short* __restrict__ ohi,
                            unsigned short* __restrict__ olo, int n)
{
    int warp = (blockIdx.x * blockDim.x + threadIdx.x) >> 5;
    int lane = threadIdx.x & 31;
    if (warp >= n) return;
    int node = warp;
    float dd  = g_dinv[node];
    int beg = g_rowptr[node], end = g_rowptr[node + 1];
    float acc[8];
#pragma unroll
    for (int j = 0; j < 8; j++) acc[j] = 0.f;
    for (int j = beg; j < end; j++) {
        int s = g_adj[j];
        float ds = g_dinv[s];
        uint4 hv = *((const uint4*)(thi + (size_t)s * DIM) + lane);
        uint4 lv = *((const uint4*)(tlo + (size_t)s * DIM) + lane);
        float2 p;
        p = recon2(hv.x, lv.x); acc[0] += ds * p.x; acc[1] += ds * p.y;
        p = recon2(hv.y, lv.y); acc[2] += ds * p.x; acc[3] += ds * p.y;
        p = recon2(hv.z, lv.z); acc[4] += ds * p.x; acc[5] += ds * p.y;
        p = recon2(hv.w, lv.w); acc[6] += ds * p.x; acc[7] += ds * p.y;
    }
    uint4 shv = *((const uint4*)(thi + (size_t)node * DIM) + lane);
    uint4 slv = *((const uint4*)(tlo + (size_t)node * DIM) + lane);
    float4 b0 = ((const float4*)bias)[lane * 2];
    float4 b1 = ((const float4*)bias)[lane * 2 + 1];
    float dd2 = dd * dd;
    float v[8];
    float2 p;
    p = recon2(shv.x, slv.x); v[0] = dd * acc[0] + dd2 * p.x + b0.x; v[1] = dd * acc[1] + dd2 * p.y + b0.y;
    p = recon2(shv.y, slv.y); v[2] = dd * acc[2] + dd2 * p.x + b0.z; v[3] = dd * acc[3] + dd2 * p.y + b0.w;
    p = recon2(shv.z, slv.z); v[4] = dd * acc[4] + dd2 * p.x + b1.x; v[5] = dd * acc[5] + dd2 * p.y + b1.y;
    p = recon2(shv.w, slv.w); v[6] = dd * acc[6] + dd2 * p.x + b1.z; v[7] = dd * acc[7] + dd2 * p.y + b1.w;
#pragma unroll
    for (int j = 0; j < 8; j++) v[j] = fmaxf(v[j], 0.f);
    uint4 oh, ol;
    split2(v[0], v[1], oh.x, ol.x);
    split2(v[2], v[3], oh.y, ol.y);
    split2(v[4], v[5], oh.z, ol.z);
    split2(v[6], v[7], oh.w, ol.w);
    *((uint4*)(ohi + (size_t)node * DIM) + lane) = oh;
    *((uint4*)(olo + (size_t)node * DIM) + lane) = ol;
}

// ==================== BN stats + fused final (planes) ======================
__global__ void k_bnreduce(const unsigned short* __restrict__ thi,
                           const unsigned short* __restrict__ tlo, int n)
{
    int f = threadIdx.x;
    float s = 0.f, q = 0.f;
    for (int r = blockIdx.x; r < n; r += gridDim.x) {
        float v = __half2float(__ushort_as_half(thi[(size_t)r * DIM + f]))
                + __half2float(__ushort_as_half(tlo[(size_t)r * DIM + f]));
        s += v; q += v * v;
    }
    atomicAdd(&g_bnsum[f], s);
    atomicAdd(&g_bnsum[DIM + f], q);
}

__global__ __launch_bounds__(256) void k_final(
    const unsigned short* __restrict__ thi, const unsigned short* __restrict__ tlo,
    const float* __restrict__ w2, const float* __restrict__ b2,
    const float* __restrict__ gamma, const float* __restrict__ beta,
    float* __restrict__ out, int n)
{
    __shared__ float sW[DIM * NCLS];
    __shared__ float sA[DIM], sB[DIM];
    __shared__ float sb2[NCLS];
    __shared__ float sH[8][DIM];
    int tid = threadIdx.x;
    for (int i = tid; i < DIM * NCLS; i += 256) sW[i] = w2[i];
    if (tid < NCLS) sb2[tid] = b2[tid];
    {
        float invn = 1.0f / (float)n;
        float mu  = g_bnsum[tid] * invn;
        float var = g_bnsum[DIM + tid] * invn - mu * mu;
        float rs  = rsqrtf(var + BN_EPS);
        float a   = rs * gamma[tid];
        sA[tid] = a;
        sB[tid] = beta[tid] - mu * a;
    }
    __syncthreads();

    int warp = tid >> 5, lane = tid & 31;
    int node = blockIdx.x * 8 + warp;
    if (node >= n) return;

    uint4 hv = *((const uint4*)(thi + (size_t)node * DIM) + lane);
    uint4 lv = *((const uint4*)(tlo + (size_t)node * DIM) + lane);
    int f0 = lane * 8;
    {
        float2 p;
        p = recon2(hv.x, lv.x);
        sH[warp][f0 + 0] = fmaxf(p.x * sA[f0 + 0] + sB[f0 + 0], 0.f);
        sH[warp][f0 + 1] = fmaxf(p.y * sA[f0 + 1] + sB[f0 + 1], 0.f);
        p = recon2(hv.y, lv.y);
        sH[warp][f0 + 2] = fmaxf(p.x * sA[f0 + 2] + sB[f0 + 2], 0.f);
        sH[warp][f0 + 3] = fmaxf(p.y * sA[f0 + 3] + sB[f0 + 3], 0.f);
        p = recon2(hv.z, lv.z);
        sH[warp][f0 + 4] = fmaxf(p.x * sA[f0 + 4] + sB[f0 + 4], 0.f);
        sH[warp][f0 + 5] = fmaxf(p.y * sA[f0 + 5] + sB[f0 + 5], 0.f);
        p = recon2(hv.w, lv.w);
        sH[warp][f0 + 6] = fmaxf(p.x * sA[f0 + 6] + sB[f0 + 6], 0.f);
        sH[warp][f0 + 7] = fmaxf(p.y * sA[f0 + 7] + sB[f0 + 7], 0.f);
    }
    __syncwarp();

    float logit = -1e30f;
    if (lane < NCLS) {
        float acc = sb2[lane];
#pragma unroll 8
        for (int f = 0; f < DIM; f++) acc += sH[warp][f] * sW[f * NCLS + lane];
        logit = acc;
    }
    float m = logit;
#pragma unroll
    for (int off = 16; off; off >>= 1) m = fmaxf(m, __shfl_xor_sync(0xffffffffu, m, off));
    float e = (lane < NCLS) ? __expf(logit - m) : 0.f;
    float ssum = e;
#pragma unroll
    for (int off = 16; off; off >>= 1) ssum += __shfl_xor_sync(0xffffffffu, ssum, off);
    if (lane < NCLS) out[(size_t)node * NCLS + lane] = e / ssum;
}

// ==================== host =================================================
extern "C" void kernel_launch(void* const* d_in, const int* in_sizes, int n_in,
                              void* d_out, int out_size)
{
    const float* x    = (const float*)d_in[0];
    const void*  ei   = d_in[1];
    const float* linw = (const float*)d_in[2];
    const float* c1w  = (const float*)d_in[3];
    const float* c1b  = (const float*)d_in[4];
    const float* c2w  = (const float*)d_in[5];
    const float* c2b  = (const float*)d_in[6];
    const float* m1w  = (const float*)d_in[7];
    const float* m1b  = (const float*)d_in[8];
    const float* gam  = (const float*)d_in[9];
    const float* bet  = (const float*)d_in[10];
    const float* m2w  = (const float*)d_in[11];
    const float* m2b  = (const float*)d_in[12];
    float* out = (float*)d_out;

    int Dd = in_sizes[4];                 // 256
    int G  = in_sizes[2] / Dd;            // 1002
    int n  = in_sizes[0] / G;             // 50000
    int E  = in_sizes[1] / 2;             // 800000

    unsigned short *xh, *xl, *pAh, *pAl, *pBh, *pBl, *whi;
    cudaGetSymbolAddress((void**)&xh,  g_xh);
    cudaGetSymbolAddress((void**)&xl,  g_xl);
    cudaGetSymbolAddress((void**)&pAh, g_pAh);
    cudaGetSymbolAddress((void**)&pAl, g_pAl);
    cudaGetSymbolAddress((void**)&pBh, g_pBh);
    cudaGetSymbolAddress((void**)&pBl, g_pBl);
    cudaGetSymbolAddress((void**)&whi, g_whi);

    const int GEMM_SMEM = 2 * STG_SZ;   // 61440
    cudaFuncSetAttribute(k_pgemm, cudaFuncAttributeMaxDynamicSharedMemorySize, GEMM_SMEM);

    const int tpb = 256;
    dim3 wblk(32, 8);
    dim3 grd(2, (n + 127) / 128);
    long long xtot = (long long)n * (KPAD0 / 2);

    k_xsplit<<<(int)((xtot + tpb - 1) / tpb), tpb>>>(x, n, G, xh, xl);
    k_wprep<<<dim3(KPAD0 / 32, 8), wblk>>>(linw, G,   KPAD0, whi + WOFF0);
    k_wprep<<<dim3(8, 8),          wblk>>>(c1w,  256, 256,   whi + WOFF1);
    k_pgemm<<<grd, 256, GEMM_SMEM>>>(xh, xl, whi + WOFF0, nullptr, pAh, pAl, n, KPAD0);
    k_wprep<<<dim3(8, 8),          wblk>>>(c2w,  256, 256,   whi + WOFF2);
    k_wprep<<<dim3(8, 8),          wblk>>>(m1w,  256, 256,   whi + WOFF3);

    int initN = (n > 2 * DIM) ? n : 2 * DIM;
    k_init<<<(initN + tpb - 1) / tpb, tpb>>>(ei, E, n);
    k_count<<<(E + tpb - 1) / tpb, tpb>>>(ei, E);
    k_scan<<<1, 1024>>>(n);
    k_fill<<<(E + tpb - 1) / tpb, tpb>>>(ei, E);

    k_pgemm<<<grd, 256, GEMM_SMEM>>>(pAh, pAl, whi + WOFF1, nullptr, pBh, pBl, n, 256);
    k_aggregate<<<(n + 7) / 8, 256>>>(pBh, pBl, c1b, pAh, pAl, n);
    k_pgemm<<<grd, 256, GEMM_SMEM>>>(pAh, pAl, whi + WOFF2, nullptr, pBh, pBl, n, 256);
    k_aggregate<<<(n + 7) / 8, 256>>>(pBh, pBl, c2b, pAh, pAl, n);
    k_pgemm<<<grd, 256, GEMM_SMEM>>>(pAh, pAl, whi + WOFF3, m1b, pBh, pBl, n, 256);
    k_bnreduce<<<256, DIM>>>(pBh, pBl, n);
    k_final<<<(n + 7) / 8, 256>>>(pBh, pBl, m2w, m2b, gam, bet, out, n);
}

// round 14
// speedup vs baseline: 1.1306x; 1.0019x over previous
#include <cuda_runtime.h>
#include <cuda_fp16.h>
#include <cstdint>

#define DIM   256
#define NCLS  20
#define MAXN  50000
#define MAXE  800000
#define BN_EPS 1e-5f
#define KPAD0 1024

// ==================== device scratch =======================================
__device__ int   g_cnt[MAXN];
__device__ int   g_rowptr[MAXN + 1];
__device__ int   g_cursor[MAXN];
__device__ int   g_adj[MAXE];
__device__ float g_dinv[MAXN];
__device__ float g_bnsum[2 * DIM];
__device__ int   g_is64;
// activation planes (hi/lo fp16 as u16) — A side of every GEMM
__device__ unsigned short g_xh[(size_t)MAXN * KPAD0];
__device__ unsigned short g_xl[(size_t)MAXN * KPAD0];
__device__ unsigned short g_pAh[(size_t)MAXN * DIM];
__device__ unsigned short g_pAl[(size_t)MAXN * DIM];
__device__ unsigned short g_pBh[(size_t)MAXN * DIM];
__device__ unsigned short g_pBl[(size_t)MAXN * DIM];
// weights: SINGLE fp16 plane [N=256][Kpad]; lin (Kpad=1024) + 3 x (Kpad=256)
#define WOFF0 0
#define WOFF1 (256 * 1024)
#define WOFF2 (WOFF1 + 256 * 256)
#define WOFF3 (WOFF2 + 256 * 256)
#define WTOT  (WOFF3 + 256 * 256)
__device__ unsigned short g_whi[WTOT];

// ==================== PTX helpers (non-'a' only!) ==========================
__device__ __forceinline__ uint32_t smem_u32(const void* p) {
    uint32_t a;
    asm("{ .reg .u64 t; cvta.to.shared.u64 t, %1; cvt.u32.u64 %0, t; }" : "=r"(a) : "l"(p));
    return a;
}
#define LDSM_X4(r, addr) \
    asm volatile("ldmatrix.sync.aligned.m8n8.x4.shared.b16 {%0,%1,%2,%3}, [%4];" \
        : "=r"((r)[0]), "=r"((r)[1]), "=r"((r)[2]), "=r"((r)[3]) : "r"(addr))
#define MMA_F16(cv, a, b0v, b1v) \
    asm volatile("mma.sync.aligned.m16n8k16.row.col.f32.f16.f16.f32 " \
        "{%0,%1,%2,%3}, {%4,%5,%6,%7}, {%8,%9}, {%0,%1,%2,%3};" \
        : "+f"((cv)[0]), "+f"((cv)[1]), "+f"((cv)[2]), "+f"((cv)[3]) \
        : "r"((a)[0]), "r"((a)[1]), "r"((a)[2]), "r"((a)[3]), "r"(b0v), "r"(b1v))
#define CP_ASYNC16(dst, src) \
    asm volatile("cp.async.cg.shared.global [%0], [%1], 16;" :: "r"(dst), "l"(src))
#define CP_COMMIT() asm volatile("cp.async.commit_group;" ::: "memory")

// split pair of f32 into packed fp16 hi (rn) + fp16 residual lo
__device__ __forceinline__ void split2(float v0, float v1, unsigned& hp, unsigned& lp) {
    __half h0 = __float2half_rn(v0), h1 = __float2half_rn(v1);
    float r0 = v0 - __half2float(h0), r1 = v1 - __half2float(h1);
    __half l0 = __float2half_rn(r0), l1 = __float2half_rn(r1);
    hp = ((unsigned)__half_as_ushort(h1) << 16) | __half_as_ushort(h0);
    lp = ((unsigned)__half_as_ushort(l1) << 16) | __half_as_ushort(l0);
}
__device__ __forceinline__ float2 recon2(unsigned h, unsigned l) {
    float2 hf = __half22float2(*(__half2*)&h);
    float2 lf = __half22float2(*(__half2*)&l);
    return make_float2(hf.x + lf.x, hf.y + lf.y);
}

// ==================== x split: fp32 [M][K] -> planes [M][1024] =============
__global__ void k_xsplit(const float* __restrict__ x, int M, int K,
                         unsigned short* __restrict__ xh, unsigned short* __restrict__ xl)
{
    long long i = (long long)blockIdx.x * blockDim.x + threadIdx.x;
    long long total = (long long)M * (KPAD0 / 2);
    if (i >= total) return;
    int row = (int)(i >> 9);
    int p   = (int)(i & 511);
    float2 v = make_float2(0.f, 0.f);
    if (2 * p + 1 < K) v = *(const float2*)(x + (size_t)row * K + 2 * p);
    else if (2 * p < K) v.x = x[(size_t)row * K + 2 * p];
    unsigned hp, lp;
    split2(v.x, v.y, hp, lp);
    ((unsigned*)xh)[(size_t)row * 512 + p] = hp;
    ((unsigned*)xl)[(size_t)row * 512 + p] = lp;
}

// ==================== init / CSR build =====================================
__global__ void k_init(const void* eiv, int E, int n) {
    int i = blockIdx.x * blockDim.x + threadIdx.x;
    if (i < n) g_cnt[i] = 0;
    if (i < 2 * DIM) g_bnsum[i] = 0.f;
    if (i == 0) {
        const long long* p = (const long long*)eiv;
        int ok = 1;
        int m = E < 64 ? E : 64;
        for (int k = 0; k < m; k++) {
            long long v = p[k];
            if (v < 0 || v >= (long long)n) { ok = 0; break; }
        }
        g_is64 = ok;
    }
}
__global__ void k_count(const void* eiv, int E) {
    int e = blockIdx.x * blockDim.x + threadIdx.x;
    if (e >= E) return;
    int d;
    if (g_is64) d = (int)((const long long*)eiv)[(size_t)E + e];
    else        d = ((const int*)eiv)[(size_t)E + e];
    atomicAdd(&g_cnt[d], 1);
}
__global__ void k_scan(int n) {
    __shared__ int part[1024];
    int t = threadIdx.x;
    int chunk = (n + 1023) >> 10;
    int beg = t * chunk;
    int end = beg + chunk; if (end > n) end = n;
    int s = 0;
    for (int i = beg; i < end; i++) s += g_cnt[i];
    part[t] = s;
    __syncthreads();
    for (int off = 1; off < 1024; off <<= 1) {
        int v = 0;
        if (t >= off) v = part[t - off];
        __syncthreads();
        part[t] += v;
        __syncthreads();
    }
    int run = (t == 0) ? 0 : part[t - 1];
    for (int i = beg; i < end; i++) {
        int c = g_cnt[i];
        g_rowptr[i] = run;
        g_cursor[i] = run;
        g_dinv[i] = rsqrtf((float)c + 1.0f);
        run += c;
    }
    if (beg < n && end == n) g_rowptr[n] = run;
}
__global__ void k_fill(const void* eiv, int E) {
    int e = blockIdx.x * blockDim.x + threadIdx.x;
    if (e >= E) return;
    int s, d;
    if (g_is64) {
        const long long* p = (const long long*)eiv;
        s = (int)p[e]; d = (int)p[(size_t)E + e];
    } else {
        const int* p = (const int*)eiv;
        s = p[e]; d = p[(size_t)E + e];
    }
    int pos = atomicAdd(&g_cursor[d], 1);
    g_adj[pos] = s;
}

// ==================== weight prep: transpose + single fp16 plane ===========
__global__ void k_wprep(const float* __restrict__ w, int K, int Kpad,
                        unsigned short* __restrict__ hi)
{
    __shared__ float t[32][33];
    int k0 = blockIdx.x * 32, n0 = blockIdx.y * 32;
    int tx = threadIdx.x, ty = threadIdx.y;   // 32 x 8
#pragma unroll
    for (int r = 0; r < 4; r++) {
        int k = k0 + ty + r * 8;
        t[ty + r * 8][tx] = (k < K) ? w[(size_t)k * 256 + n0 + tx] : 0.f;
    }
    __syncthreads();
#pragma unroll
    for (int r = 0; r < 4; r++) {
        int nn = n0 + ty + r * 8;
        int k  = k0 + tx;
        hi[(size_t)nn * Kpad + k] = __half_as_ushort(__float2half_rn(t[tx][ty + r * 8]));
    }
}

// ==================== plane GEMM: C = A @ W^T ==============================
// A planes fp16 hi/lo [M][Kpad]; B single fp16 plane [256][Kpad].
// 2 MMAs per fragment set: (Ah + Al) x Bh.  CTA 128x128, 8 warps 4(M)x2(N),
// BK=32, 2-stage, one barrier/iter.  MMA order interleaved for ILP:
// per np-pair, all ah-round MMAs (8) then all al-round MMAs (8) — same-
// accumulator RAW distance 8 instead of 1.
#define SM_P 80
#define SM_A_H 0
#define SM_A_L 10240
#define SM_B_H 20480
#define STG_SZ 30720
__global__ __launch_bounds__(256, 2) void k_pgemm(
    const unsigned short* __restrict__ Ahi, const unsigned short* __restrict__ Alo,
    const unsigned short* __restrict__ Bhi,
    const float* __restrict__ bias,
    unsigned short* __restrict__ Chi, unsigned short* __restrict__ Clo,
    int M, int Kpad)
{
    extern __shared__ __align__(16) unsigned char sm[];
    uint32_t sb = smem_u32(sm);
    int tid = threadIdx.x, wid = tid >> 5, lane = tid & 31;
    int row0 = blockIdx.y * 128;
    int c0   = blockIdx.x * 128;
    int wm = wid & 3, wn = wid >> 2;

    float cacc[2][8][4];
#pragma unroll
    for (int a = 0; a < 2; a++)
#pragma unroll
        for (int b = 0; b < 8; b++)
#pragma unroll
            for (int d = 0; d < 4; d++) cacc[a][b][d] = 0.f;

    // loader mapping: 2 threads per row, 16 u16 (32B) each
    int arow = tid >> 1;
    int half = tid & 1;
    bool aOK = (row0 + arow) < M;
    const unsigned short* AhB = Ahi + (size_t)(row0 + arow) * Kpad + half * 16;
    const unsigned short* AlB = Alo + (size_t)(row0 + arow) * Kpad + half * 16;
    const unsigned short* BhB = Bhi + (size_t)(c0 + arow) * Kpad + half * 16;
    uint32_t sOff = (uint32_t)(arow * SM_P + half * 32);

    // ldmatrix lane addresses (R5-proven layout)
    uint32_t aOff = (uint32_t)((wm * 32 + (lane & 15)) * SM_P + (lane >> 4) * 16);
    uint32_t bOff = (uint32_t)((wn * 64 + (lane & 7) + ((lane >> 4) & 1) * 8) * SM_P
                               + ((lane >> 3) & 1) * 16);

#define ISSUE_STAGE(stg_, kb_) do { \
    if (aOK) { \
        CP_ASYNC16((stg_) + SM_A_H + sOff,      AhB + (kb_)); \
        CP_ASYNC16((stg_) + SM_A_H + sOff + 16, AhB + (kb_) + 8); \
        CP_ASYNC16((stg_) + SM_A_L + sOff,      AlB + (kb_)); \
        CP_ASYNC16((stg_) + SM_A_L + sOff + 16, AlB + (kb_) + 8); \
    } \
    CP_ASYNC16((stg_) + SM_B_H + sOff,      BhB + (kb_)); \
    CP_ASYNC16((stg_) + SM_B_H + sOff + 16, BhB + (kb_) + 8); \
} while (0)

    int NB = Kpad >> 5;
    ISSUE_STAGE(sb, 0);
    CP_COMMIT();

    for (int ib = 0; ib < NB; ib++) {
        uint32_t cur = sb + (uint32_t)(ib & 1) * STG_SZ;
        asm volatile("cp.async.wait_group 0;" ::: "memory");  // cur loads done
        __syncthreads();   // + everyone finished reading the other buffer
        if (ib + 1 < NB) {
            uint32_t nst = sb + (uint32_t)((ib + 1) & 1) * STG_SZ;
            ISSUE_STAGE(nst, (ib + 1) << 5);
            CP_COMMIT();   // overlaps the compute below
        }
        // ---- compute: 2 k-frags; per np-pair: ah round (8 MMA) then al round
#pragma unroll
        for (int kf = 0; kf < 2; kf++) {
            uint32_t ah[2][4], al[2][4];
#pragma unroll
            for (int mf = 0; mf < 2; mf++) {
                uint32_t addr = cur + aOff + (uint32_t)(mf * 16 * SM_P + kf * 32);
                LDSM_X4(ah[mf], addr + SM_A_H);
                LDSM_X4(al[mf], addr + SM_A_L);
            }
#pragma unroll
            for (int nph = 0; nph < 2; nph++) {
                int np0 = nph * 2, np1 = nph * 2 + 1;
                uint32_t b0[4], b1[4];
                uint32_t addr0 = cur + bOff + (uint32_t)(np0 * 16 * SM_P + kf * 32);
                uint32_t addr1 = cur + bOff + (uint32_t)(np1 * 16 * SM_P + kf * 32);
                LDSM_X4(b0, addr0 + SM_B_H);
                LDSM_X4(b1, addr1 + SM_B_H);
                // ah round — 8 independent MMAs across 8 distinct accumulators
                MMA_F16(cacc[0][np0 * 2],     ah[0], b0[0], b0[1]);
                MMA_F16(cacc[1][np0 * 2],     ah[1], b0[0], b0[1]);
                MMA_F16(cacc[0][np0 * 2 + 1], ah[0], b0[2], b0[3]);
                MMA_F16(cacc[1][np0 * 2 + 1], ah[1], b0[2], b0[3]);
                MMA_F16(cacc[0][np1 * 2],     ah[0], b1[0], b1[1]);
                MMA_F16(cacc[1][np1 * 2],     ah[1], b1[0], b1[1]);
                MMA_F16(cacc[0][np1 * 2 + 1], ah[0], b1[2], b1[3]);
                MMA_F16(cacc[1][np1 * 2 + 1], ah[1], b1[2], b1[3]);
                // al round — same accumulators, RAW distance 8
                MMA_F16(cacc[0][np0 * 2],     al[0], b0[0], b0[1]);
                MMA_F16(cacc[1][np0 * 2],     al[1], b0[0], b0[1]);
                MMA_F16(cacc[0][np0 * 2 + 1], al[0], b0[2], b0[3]);
                MMA_F16(cacc[1][np0 * 2 + 1], al[1], b0[2], b0[3]);
                MMA_F16(cacc[0][np1 * 2],     al[0], b1[0], b1[1]);
                MMA_F16(cacc[1][np1 * 2],     al[1], b1[0], b1[1]);
                MMA_F16(cacc[0][np1 * 2 + 1], al[0], b1[2], b1[3]);
                MMA_F16(cacc[1][np1 * 2 + 1], al[1], b1[2], b1[3]);
            }
        }
    }
#undef ISSUE_STAGE

    // ---- epilogue: write output planes
    int g = lane >> 2, tq = lane & 3;
#pragma unroll
    for (int mf = 0; mf < 2; mf++) {
        int r = row0 + wm * 32 + mf * 16 + g;
#pragma unroll
        for (int nf = 0; nf < 8; nf++) {
            int cc = c0 + wn * 64 + nf * 8 + tq * 2;
            float b0 = 0.f, b1 = 0.f;
            if (bias) { b0 = __ldg(bias + cc); b1 = __ldg(bias + cc + 1); }
            float v0 = cacc[mf][nf][0] + b0, v1 = cacc[mf][nf][1] + b1;
            float v2 = cacc[mf][nf][2] + b0, v3 = cacc[mf][nf][3] + b1;
            unsigned hp, lp;
            if (r < M) {
                split2(v0, v1, hp, lp);
                *(unsigned*)(Chi + (size_t)r * 256 + cc) = hp;
                *(unsigned*)(Clo + (size_t)r * 256 + cc) = lp;
            }
            if (r + 8 < M) {
                split2(v2, v3, hp, lp);
                *(unsigned*)(Chi + (size_t)(r + 8) * 256 + cc) = hp;
                *(unsigned*)(Clo + (size_t)(r + 8) * 256 + cc) = lp;
            }
        }
    }
}

// ==================== GCN aggregation (warp per node, planes) ==============
__global__ void k_aggregate(const unsigned short* __restrict__ thi,
                            const unsigned short* __restrict__ tlo,
                            const float* __restrict__ bias,
                            unsigned short* __restrict__ ohi,
                            unsigned short* __restrict__ olo, int n)
{
    int warp = (blockIdx.x * blockDim.x + threadIdx.x) >> 5;
    int lane = threadIdx.x & 31;
    if (warp >= n) return;
    int node = warp;
    float dd  = g_dinv[node];
    int beg = g_rowptr[node], end = g_rowptr[node + 1];
    float acc[8];
#pragma unroll
    for (int j = 0; j < 8; j++) acc[j] = 0.f;
    for (int j = beg; j < end; j++) {
        int s = g_adj[j];
        float ds = g_dinv[s];
        uint4 hv = *((const uint4*)(thi + (size_t)s * DIM) + lane);
        uint4 lv = *((const uint4*)(tlo + (size_t)s * DIM) + lane);
        float2 p;
        p = recon2(hv.x, lv.x); acc[0] += ds * p.x; acc[1] += ds * p.y;
        p = recon2(hv.y, lv.y); acc[2] += ds * p.x; acc[3] += ds * p.y;
        p = recon2(hv.z, lv.z); acc[4] += ds * p.x; acc[5] += ds * p.y;
        p = recon2(hv.w, lv.w); acc[6] += ds * p.x; acc[7] += ds * p.y;
    }
    uint4 shv = *((const uint4*)(thi + (size_t)node * DIM) + lane);
    uint4 slv = *((const uint4*)(tlo + (size_t)node * DIM) + lane);
    float4 b0 = ((const float4*)bias)[lane * 2];
    float4 b1 = ((const float4*)bias)[lane * 2 + 1];
    float dd2 = dd * dd;
    float v[8];
    float2 p;
    p = recon2(shv.x, slv.x); v[0] = dd * acc[0] + dd2 * p.x + b0.x; v[1] = dd * acc[1] + dd2 * p.y + b0.y;
    p = recon2(shv.y, slv.y); v[2] = dd * acc[2] + dd2 * p.x + b0.z; v[3] = dd * acc[3] + dd2 * p.y + b0.w;
    p = recon2(shv.z, slv.z); v[4] = dd * acc[4] + dd2 * p.x + b1.x; v[5] = dd * acc[5] + dd2 * p.y + b1.y;
    p = recon2(shv.w, slv.w); v[6] = dd * acc[6] + dd2 * p.x + b1.z; v[7] = dd * acc[7] + dd2 * p.y + b1.w;
#pragma unroll
    for (int j = 0; j < 8; j++) v[j] = fmaxf(v[j], 0.f);
    uint4 oh, ol;
    split2(v[0], v[1], oh.x, ol.x);
    split2(v[2], v[3], oh.y, ol.y);
    split2(v[4], v[5], oh.z, ol.z);
    split2(v[6], v[7], oh.w, ol.w);
    *((uint4*)(ohi + (size_t)node * DIM) + lane) = oh;
    *((uint4*)(olo + (size_t)node * DIM) + lane) = ol;
}

// ==================== BN stats + fused final (planes) ======================
__global__ void k_bnreduce(const unsigned short* __restrict__ thi,
                           const unsigned short* __restrict__ tlo, int n)
{
    int f = threadIdx.x;
    float s = 0.f, q = 0.f;
    for (int r = blockIdx.x; r < n; r += gridDim.x) {
        float v = __half2float(__ushort_as_half(thi[(size_t)r * DIM + f]))
                + __half2float(__ushort_as_half(tlo[(size_t)r * DIM + f]));
        s += v; q += v * v;
    }
    atomicAdd(&g_bnsum[f], s);
    atomicAdd(&g_bnsum[DIM + f], q);
}

__global__ __launch_bounds__(256) void k_final(
    const unsigned short* __restrict__ thi, const unsigned short* __restrict__ tlo,
    const float* __restrict__ w2, const float* __restrict__ b2,
    const float* __restrict__ gamma, const float* __restrict__ beta,
    float* __restrict__ out, int n)
{
    __shared__ float sW[DIM * NCLS];
    __shared__ float sA[DIM], sB[DIM];
    __shared__ float sb2[NCLS];
    __shared__ float sH[8][DIM];
    int tid = threadIdx.x;
    for (int i = tid; i < DIM * NCLS; i += 256) sW[i] = w2[i];
    if (tid < NCLS) sb2[tid] = b2[tid];
    {
        float invn = 1.0f / (float)n;
        float mu  = g_bnsum[tid] * invn;
        float var = g_bnsum[DIM + tid] * invn - mu * mu;
        float rs  = rsqrtf(var + BN_EPS);
        float a   = rs * gamma[tid];
        sA[tid] = a;
        sB[tid] = beta[tid] - mu * a;
    }
    __syncthreads();

    int warp = tid >> 5, lane = tid & 31;
    int node = blockIdx.x * 8 + warp;
    if (node >= n) return;

    uint4 hv = *((const uint4*)(thi + (size_t)node * DIM) + lane);
    uint4 lv = *((const uint4*)(tlo + (size_t)node * DIM) + lane);
    int f0 = lane * 8;
    {
        float2 p;
        p = recon2(hv.x, lv.x);
        sH[warp][f0 + 0] = fmaxf(p.x * sA[f0 + 0] + sB[f0 + 0], 0.f);
        sH[warp][f0 + 1] = fmaxf(p.y * sA[f0 + 1] + sB[f0 + 1], 0.f);
        p = recon2(hv.y, lv.y);
        sH[warp][f0 + 2] = fmaxf(p.x * sA[f0 + 2] + sB[f0 + 2], 0.f);
        sH[warp][f0 + 3] = fmaxf(p.y * sA[f0 + 3] + sB[f0 + 3], 0.f);
        p = recon2(hv.z, lv.z);
        sH[warp][f0 + 4] = fmaxf(p.x * sA[f0 + 4] + sB[f0 + 4], 0.f);
        sH[warp][f0 + 5] = fmaxf(p.y * sA[f0 + 5] + sB[f0 + 5], 0.f);
        p = recon2(hv.w, lv.w);
        sH[warp][f0 + 6] = fmaxf(p.x * sA[f0 + 6] + sB[f0 + 6], 0.f);
        sH[warp][f0 + 7] = fmaxf(p.y * sA[f0 + 7] + sB[f0 + 7], 0.f);
    }
    __syncwarp();

    float logit = -1e30f;
    if (lane < NCLS) {
        float acc = sb2[lane];
#pragma unroll 8
        for (int f = 0; f < DIM; f++) acc += sH[warp][f] * sW[f * NCLS + lane];
        logit = acc;
    }
    float m = logit;
#pragma unroll
    for (int off = 16; off; off >>= 1) m = fmaxf(m, __shfl_xor_sync(0xffffffffu, m, off));
    float e = (lane < NCLS) ? __expf(logit - m) : 0.f;
    float ssum = e;
#pragma unroll
    for (int off = 16; off; off >>= 1) ssum += __shfl_xor_sync(0xffffffffu, ssum, off);
    if (lane < NCLS) out[(size_t)node * NCLS + lane] = e / ssum;
}

// ==================== host =================================================
extern "C" void kernel_launch(void* const* d_in, const int* in_sizes, int n_in,
                              void* d_out, int out_size)
{
    const float* x    = (const float*)d_in[0];
    const void*  ei   = d_in[1];
    const float* linw = (const float*)d_in[2];
    const float* c1w  = (const float*)d_in[3];
    const float* c1b  = (const float*)d_in[4];
    const float* c2w  = (const float*)d_in[5];
    const float* c2b  = (const float*)d_in[6];
    const float* m1w  = (const float*)d_in[7];
    const float* m1b  = (const float*)d_in[8];
    const float* gam  = (const float*)d_in[9];
    const float* bet  = (const float*)d_in[10];
    const float* m2w  = (const float*)d_in[11];
    const float* m2b  = (const float*)d_in[12];
    float* out = (float*)d_out;

    int Dd = in_sizes[4];                 // 256
    int G  = in_sizes[2] / Dd;            // 1002
    int n  = in_sizes[0] / G;             // 50000
    int E  = in_sizes[1] / 2;             // 800000

    unsigned short *xh, *xl, *pAh, *pAl, *pBh, *pBl, *whi;
    cudaGetSymbolAddress((void**)&xh,  g_xh);
    cudaGetSymbolAddress((void**)&xl,  g_xl);
    cudaGetSymbolAddress((void**)&pAh, g_pAh);
    cudaGetSymbolAddress((void**)&pAl, g_pAl);
    cudaGetSymbolAddress((void**)&pBh, g_pBh);
    cudaGetSymbolAddress((void**)&pBl, g_pBl);
    cudaGetSymbolAddress((void**)&whi, g_whi);

    const int GEMM_SMEM = 2 * STG_SZ;   // 61440
    cudaFuncSetAttribute(k_pgemm, cudaFuncAttributeMaxDynamicSharedMemorySize, GEMM_SMEM);

    const int tpb = 256;
    dim3 wblk(32, 8);
    dim3 grd(2, (n + 127) / 128);
    long long xtot = (long long)n * (KPAD0 / 2);

    k_xsplit<<<(int)((xtot + tpb - 1) / tpb), tpb>>>(x, n, G, xh, xl);
    k_wprep<<<dim3(KPAD0 / 32, 8), wblk>>>(linw, G,   KPAD0, whi + WOFF0);
    k_wprep<<<dim3(8, 8),          wblk>>>(c1w,  256, 256,   whi + WOFF1);
    k_pgemm<<<grd, 256, GEMM_SMEM>>>(xh, xl, whi + WOFF0, nullptr, pAh, pAl, n, KPAD0);
    k_wprep<<<dim3(8, 8),          wblk>>>(c2w,  256, 256,   whi + WOFF2);
    k_wprep<<<dim3(8, 8),          wblk>>>(m1w,  256, 256,   whi + WOFF3);

    int initN = (n > 2 * DIM) ? n : 2 * DIM;
    k_init<<<(initN + tpb - 1) / tpb, tpb>>>(ei, E, n);
    k_count<<<(E + tpb - 1) / tpb, tpb>>>(ei, E);
    k_scan<<<1, 1024>>>(n);
    k_fill<<<(E + tpb - 1) / tpb, tpb>>>(ei, E);

    k_pgemm<<<grd, 256, GEMM_SMEM>>>(pAh, pAl, whi + WOFF1, nullptr, pBh, pBl, n, 256);
    k_aggregate<<<(n + 7) / 8, 256>>>(pBh, pBl, c1b, pAh, pAl, n);
    k_pgemm<<<grd, 256, GEMM_SMEM>>>(pAh, pAl, whi + WOFF2, nullptr, pBh, pBl, n, 256);
    k_aggregate<<<(n + 7) / 8, 256>>>(pBh, pBl, c2b, pAh, pAl, n);
    k_pgemm<<<grd, 256, GEMM_SMEM>>>(pAh, pAl, whi + WOFF3, m1b, pBh, pBl, n, 256);
    k_bnreduce<<<256, DIM>>>(pBh, pBl, n);
    k_final<<<(n + 7) / 8, 256>>>(pBh, pBl, m2w, m2b, gam, bet, out, n);
}

// round 16
// speedup vs baseline: 1.4129x; 1.2497x over previous
#include <cuda_runtime.h>
#include <cuda_fp16.h>
#include <cstdint>

#define DIM   256
#define NCLS  20
#define MAXN  50000
#define MAXE  800000
#define BN_EPS 1e-5f
#define KPAD0 1024

// ==================== device scratch =======================================
__device__ int   g_cnt[MAXN];
__device__ int   g_rowptr[MAXN + 1];
__device__ int   g_cursor[MAXN];
__device__ int   g_adj[MAXE];
__device__ float g_dinv[MAXN];
__device__ float g_bnsum[2 * DIM];
__device__ int   g_is64;
// activations: SINGLE fp16 plane (fp32 accumulate in MMA keeps precision)
__device__ unsigned short g_xh[(size_t)MAXN * KPAD0];
__device__ unsigned short g_pA[(size_t)MAXN * DIM];
__device__ unsigned short g_pB[(size_t)MAXN * DIM];
// weights: single fp16 plane [N=256][Kpad]; lin (Kpad=1024) + 3 x (Kpad=256)
#define WOFF0 0
#define WOFF1 (256 * 1024)
#define WOFF2 (WOFF1 + 256 * 256)
#define WOFF3 (WOFF2 + 256 * 256)
#define WTOT  (WOFF3 + 256 * 256)
__device__ unsigned short g_whi[WTOT];

// ==================== PTX helpers (non-'a' only!) ==========================
__device__ __forceinline__ uint32_t smem_u32(const void* p) {
    uint32_t a;
    asm("{ .reg .u64 t; cvta.to.shared.u64 t, %1; cvt.u32.u64 %0, t; }" : "=r"(a) : "l"(p));
    return a;
}
#define LDSM_X4(r, addr) \
    asm volatile("ldmatrix.sync.aligned.m8n8.x4.shared.b16 {%0,%1,%2,%3}, [%4];" \
        : "=r"((r)[0]), "=r"((r)[1]), "=r"((r)[2]), "=r"((r)[3]) : "r"(addr))
#define MMA_F16(cv, a, b0v, b1v) \
    asm volatile("mma.sync.aligned.m16n8k16.row.col.f32.f16.f16.f32 " \
        "{%0,%1,%2,%3}, {%4,%5,%6,%7}, {%8,%9}, {%0,%1,%2,%3};" \
        : "+f"((cv)[0]), "+f"((cv)[1]), "+f"((cv)[2]), "+f"((cv)[3]) \
        : "r"((a)[0]), "r"((a)[1]), "r"((a)[2]), "r"((a)[3]), "r"(b0v), "r"(b1v))
#define CP_ASYNC16(dst, src) \
    asm volatile("cp.async.cg.shared.global [%0], [%1], 16;" :: "r"(dst), "l"(src))
#define CP_COMMIT() asm volatile("cp.async.commit_group;" ::: "memory")

__device__ __forceinline__ unsigned packh2(float v0, float v1) {
    __half2 h = __floats2half2_rn(v0, v1);
    return *(unsigned*)&h;
}

// ==================== x half: fp32 [M][K] -> fp16 [M][1024] ================
__global__ void k_xhalf(const float* __restrict__ x, int M, int K,
                        unsigned short* __restrict__ xh)
{
    long long i = (long long)blockIdx.x * blockDim.x + threadIdx.x;
    long long total = (long long)M * (KPAD0 / 2);
    if (i >= total) return;
    int row = (int)(i >> 9);
    int p   = (int)(i & 511);
    float2 v = make_float2(0.f, 0.f);
    if (2 * p + 1 < K) v = *(const float2*)(x + (size_t)row * K + 2 * p);
    else if (2 * p < K) v.x = x[(size_t)row * K + 2 * p];
    ((unsigned*)xh)[(size_t)row * 512 + p] = packh2(v.x, v.y);
}

// ==================== init / CSR build =====================================
__global__ void k_init(const void* eiv, int E, int n) {
    int i = blockIdx.x * blockDim.x + threadIdx.x;
    if (i < n) g_cnt[i] = 0;
    if (i < 2 * DIM) g_bnsum[i] = 0.f;
    if (i == 0) {
        const long long* p = (const long long*)eiv;
        int ok = 1;
        int m = E < 64 ? E : 64;
        for (int k = 0; k < m; k++) {
            long long v = p[k];
            if (v < 0 || v >= (long long)n) { ok = 0; break; }
        }
        g_is64 = ok;
    }
}
__global__ void k_count(const void* eiv, int E) {
    int e = blockIdx.x * blockDim.x + threadIdx.x;
    if (e >= E) return;
    int d;
    if (g_is64) d = (int)((const long long*)eiv)[(size_t)E + e];
    else        d = ((const int*)eiv)[(size_t)E + e];
    atomicAdd(&g_cnt[d], 1);
}
__global__ void k_scan(int n) {
    __shared__ int part[1024];
    int t = threadIdx.x;
    int chunk = (n + 1023) >> 10;
    int beg = t * chunk;
    int end = beg + chunk; if (end > n) end = n;
    int s = 0;
    for (int i = beg; i < end; i++) s += g_cnt[i];
    part[t] = s;
    __syncthreads();
    for (int off = 1; off < 1024; off <<= 1) {
        int v = 0;
        if (t >= off) v = part[t - off];
        __syncthreads();
        part[t] += v;
        __syncthreads();
    }
    int run = (t == 0) ? 0 : part[t - 1];
    for (int i = beg; i < end; i++) {
        int c = g_cnt[i];
        g_rowptr[i] = run;
        g_cursor[i] = run;
        g_dinv[i] = rsqrtf((float)c + 1.0f);
        run += c;
    }
    if (beg < n && end == n) g_rowptr[n] = run;
}
__global__ void k_fill(const void* eiv, int E) {
    int e = blockIdx.x * blockDim.x + threadIdx.x;
    if (e >= E) return;
    int s, d;
    if (g_is64) {
        const long long* p = (const long long*)eiv;
        s = (int)p[e]; d = (int)p[(size_t)E + e];
    } else {
        const int* p = (const int*)eiv;
        s = p[e]; d = p[(size_t)E + e];
    }
    int pos = atomicAdd(&g_cursor[d], 1);
    g_adj[pos] = s;
}

// ==================== weight prep: transpose + single fp16 plane ===========
__global__ void k_wprep(const float* __restrict__ w, int K, int Kpad,
                        unsigned short* __restrict__ hi)
{
    __shared__ float t[32][33];
    int k0 = blockIdx.x * 32, n0 = blockIdx.y * 32;
    int tx = threadIdx.x, ty = threadIdx.y;   // 32 x 8
#pragma unroll
    for (int r = 0; r < 4; r++) {
        int k = k0 + ty + r * 8;
        t[ty + r * 8][tx] = (k < K) ? w[(size_t)k * 256 + n0 + tx] : 0.f;
    }
    __syncthreads();
#pragma unroll
    for (int r = 0; r < 4; r++) {
        int nn = n0 + ty + r * 8;
        int k  = k0 + tx;
        hi[(size_t)nn * Kpad + k] = __half_as_ushort(__float2half_rn(t[tx][ty + r * 8]));
    }
}

// ==================== fp16 GEMM: C = A @ W^T (fp32 accumulate) =============
// A fp16 [M][Kpad]; B fp16 [256][Kpad]; C fp16 [M][256].
// CTA 128x128, 8 warps 4(M)x2(N), BK=32, 2-stage cp.async, 1 barrier/iter.
#define SM_P 80
#define SM_A 0
#define SM_B 10240
#define STG_SZ 20480
__global__ __launch_bounds__(256, 2) void k_pgemm(
    const unsigned short* __restrict__ Ah,
    const unsigned short* __restrict__ Bh,
    const float* __restrict__ bias,
    unsigned short* __restrict__ Ch,
    int M, int Kpad)
{
    extern __shared__ __align__(16) unsigned char sm[];
    uint32_t sb = smem_u32(sm);
    int tid = threadIdx.x, wid = tid >> 5, lane = tid & 31;
    int row0 = blockIdx.y * 128;
    int c0   = blockIdx.x * 128;
    int wm = wid & 3, wn = wid >> 2;

    float cacc[2][8][4];
#pragma unroll
    for (int a = 0; a < 2; a++)
#pragma unroll
        for (int b = 0; b < 8; b++)
#pragma unroll
            for (int d = 0; d < 4; d++) cacc[a][b][d] = 0.f;

    // loader: 2 threads per row, 32B (16 halves) each
    int arow = tid >> 1;
    int half = tid & 1;
    bool aOK = (row0 + arow) < M;
    const unsigned short* AhB = Ah + (size_t)(row0 + arow) * Kpad + half * 16;
    const unsigned short* BhB = Bh + (size_t)(c0 + arow) * Kpad + half * 16;
    uint32_t sOff = (uint32_t)(arow * SM_P + half * 32);

    // ldmatrix lane addresses (R5-proven layout)
    uint32_t aOff = (uint32_t)((wm * 32 + (lane & 15)) * SM_P + (lane >> 4) * 16);
    uint32_t bOff = (uint32_t)((wn * 64 + (lane & 7) + ((lane >> 4) & 1) * 8) * SM_P
                               + ((lane >> 3) & 1) * 16);

#define ISSUE_STAGE(stg_, kb_) do { \
    if (aOK) { \
        CP_ASYNC16((stg_) + SM_A + sOff,      AhB + (kb_)); \
        CP_ASYNC16((stg_) + SM_A + sOff + 16, AhB + (kb_) + 8); \
    } \
    CP_ASYNC16((stg_) + SM_B + sOff,      BhB + (kb_)); \
    CP_ASYNC16((stg_) + SM_B + sOff + 16, BhB + (kb_) + 8); \
} while (0)

    int NB = Kpad >> 5;
    ISSUE_STAGE(sb, 0);
    CP_COMMIT();

    for (int ib = 0; ib < NB; ib++) {
        uint32_t cur = sb + (uint32_t)(ib & 1) * STG_SZ;
        asm volatile("cp.async.wait_group 0;" ::: "memory");  // cur loads done
        __syncthreads();   // + everyone finished reading the other buffer
        if (ib + 1 < NB) {
            uint32_t nst = sb + (uint32_t)((ib + 1) & 1) * STG_SZ;
            ISSUE_STAGE(nst, (ib + 1) << 5);
            CP_COMMIT();   // overlaps compute below
        }
        // ---- compute: 2 k-frags x 16 MMAs
#pragma unroll
        for (int kf = 0; kf < 2; kf++) {
            uint32_t a[2][4];
#pragma unroll
            for (int mf = 0; mf < 2; mf++) {
                uint32_t addr = cur + SM_A + aOff + (uint32_t)(mf * 16 * SM_P + kf * 32);
                LDSM_X4(a[mf], addr);
            }
#pragma unroll
            for (int nph = 0; nph < 2; nph++) {
                int np0 = nph * 2, np1 = nph * 2 + 1;
                uint32_t b0[4], b1[4];
                LDSM_X4(b0, cur + SM_B + bOff + (uint32_t)(np0 * 16 * SM_P + kf * 32));
                LDSM_X4(b1, cur + SM_B + bOff + (uint32_t)(np1 * 16 * SM_P + kf * 32));
                MMA_F16(cacc[0][np0 * 2],     a[0], b0[0], b0[1]);
                MMA_F16(cacc[1][np0 * 2],     a[1], b0[0], b0[1]);
                MMA_F16(cacc[0][np0 * 2 + 1], a[0], b0[2], b0[3]);
                MMA_F16(cacc[1][np0 * 2 + 1], a[1], b0[2], b0[3]);
                MMA_F16(cacc[0][np1 * 2],     a[0], b1[0], b1[1]);
                MMA_F16(cacc[1][np1 * 2],     a[1], b1[0], b1[1]);
                MMA_F16(cacc[0][np1 * 2 + 1], a[0], b1[2], b1[3]);
                MMA_F16(cacc[1][np1 * 2 + 1], a[1], b1[2], b1[3]);
            }
        }
    }
#undef ISSUE_STAGE

    // ---- epilogue: fp16 output
    int g = lane >> 2, tq = lane & 3;
#pragma unroll
    for (int mf = 0; mf < 2; mf++) {
        int r = row0 + wm * 32 + mf * 16 + g;
#pragma unroll
        for (int nf = 0; nf < 8; nf++) {
            int cc = c0 + wn * 64 + nf * 8 + tq * 2;
            float b0 = 0.f, b1 = 0.f;
            if (bias) { b0 = __ldg(bias + cc); b1 = __ldg(bias + cc + 1); }
            if (r < M)
                *(unsigned*)(Ch + (size_t)r * 256 + cc) =
                    packh2(cacc[mf][nf][0] + b0, cacc[mf][nf][1] + b1);
            if (r + 8 < M)
                *(unsigned*)(Ch + (size_t)(r + 8) * 256 + cc) =
                    packh2(cacc[mf][nf][2] + b0, cacc[mf][nf][3] + b1);
        }
    }
}

// ==================== GCN aggregation (warp per node, fp16 rows) ===========
__global__ void k_aggregate(const unsigned short* __restrict__ t,
                            const float* __restrict__ bias,
                            unsigned short* __restrict__ o, int n)
{
    int warp = (blockIdx.x * blockDim.x + threadIdx.x) >> 5;
    int lane = threadIdx.x & 31;
    if (warp >= n) return;
    int node = warp;
    float dd  = g_dinv[node];
    int beg = g_rowptr[node], end = g_rowptr[node + 1];
    float acc[8];
#pragma unroll
    for (int j = 0; j < 8; j++) acc[j] = 0.f;
    for (int j = beg; j < end; j++) {
        int s = g_adj[j];
        float ds = g_dinv[s];
        uint4 hv = *((const uint4*)(t + (size_t)s * DIM) + lane);
        float2 p;
        p = __half22float2(*(__half2*)&hv.x); acc[0] += ds * p.x; acc[1] += ds * p.y;
        p = __half22float2(*(__half2*)&hv.y); acc[2] += ds * p.x; acc[3] += ds * p.y;
        p = __half22float2(*(__half2*)&hv.z); acc[4] += ds * p.x; acc[5] += ds * p.y;
        p = __half22float2(*(__half2*)&hv.w); acc[6] += ds * p.x; acc[7] += ds * p.y;
    }
    uint4 shv = *((const uint4*)(t + (size_t)node * DIM) + lane);
    float4 b0 = ((const float4*)bias)[lane * 2];
    float4 b1 = ((const float4*)bias)[lane * 2 + 1];
    float dd2 = dd * dd;
    float v[8];
    float2 p;
    p = __half22float2(*(__half2*)&shv.x);
    v[0] = dd * acc[0] + dd2 * p.x + b0.x; v[1] = dd * acc[1] + dd2 * p.y + b0.y;
    p = __half22float2(*(__half2*)&shv.y);
    v[2] = dd * acc[2] + dd2 * p.x + b0.z; v[3] = dd * acc[3] + dd2 * p.y + b0.w;
    p = __half22float2(*(__half2*)&shv.z);
    v[4] = dd * acc[4] + dd2 * p.x + b1.x; v[5] = dd * acc[5] + dd2 * p.y + b1.y;
    p = __half22float2(*(__half2*)&shv.w);
    v[6] = dd * acc[6] + dd2 * p.x + b1.z; v[7] = dd * acc[7] + dd2 * p.y + b1.w;
#pragma unroll
    for (int j = 0; j < 8; j++) v[j] = fmaxf(v[j], 0.f);
    uint4 ov;
    ov.x = packh2(v[0], v[1]);
    ov.y = packh2(v[2], v[3]);
    ov.z = packh2(v[4], v[5]);
    ov.w = packh2(v[6], v[7]);
    *((uint4*)(o + (size_t)node * DIM) + lane) = ov;
}

// ==================== BN stats + fused final (fp16 input) ==================
__global__ void k_bnreduce(const unsigned short* __restrict__ t, int n) {
    int f = threadIdx.x;
    float s = 0.f, q = 0.f;
    for (int r = blockIdx.x; r < n; r += gridDim.x) {
        float v = __half2float(__ushort_as_half(t[(size_t)r * DIM + f]));
        s += v; q += v * v;
    }
    atomicAdd(&g_bnsum[f], s);
    atomicAdd(&g_bnsum[DIM + f], q);
}

__global__ __launch_bounds__(256) void k_final(
    const unsigned short* __restrict__ t,
    const float* __restrict__ w2, const float* __restrict__ b2,
    const float* __restrict__ gamma, const float* __restrict__ beta,
    float* __restrict__ out, int n)
{
    __shared__ float sW[DIM * NCLS];
    __shared__ float sA[DIM], sB[DIM];
    __shared__ float sb2[NCLS];
    __shared__ float sH[8][DIM];
    int tid = threadIdx.x;
    for (int i = tid; i < DIM * NCLS; i += 256) sW[i] = w2[i];
    if (tid < NCLS) sb2[tid] = b2[tid];
    {
        float invn = 1.0f / (float)n;
        float mu  = g_bnsum[tid] * invn;
        float var = g_bnsum[DIM + tid] * invn - mu * mu;
        float rs  = rsqrtf(var + BN_EPS);
        float a   = rs * gamma[tid];
        sA[tid] = a;
        sB[tid] = beta[tid] - mu * a;
    }
    __syncthreads();

    int warp = tid >> 5, lane = tid & 31;
    int node = blockIdx.x * 8 + warp;
    if (node >= n) return;

    uint4 hv = *((const uint4*)(t + (size_t)node * DIM) + lane);
    int f0 = lane * 8;
    {
        float2 p;
        p = __half22float2(*(__half2*)&hv.x);
        sH[warp][f0 + 0] = fmaxf(p.x * sA[f0 + 0] + sB[f0 + 0], 0.f);
        sH[warp][f0 + 1] = fmaxf(p.y * sA[f0 + 1] + sB[f0 + 1], 0.f);
        p = __half22float2(*(__half2*)&hv.y);
        sH[warp][f0 + 2] = fmaxf(p.x * sA[f0 + 2] + sB[f0 + 2], 0.f);
        sH[warp][f0 + 3] = fmaxf(p.y * sA[f0 + 3] + sB[f0 + 3], 0.f);
        p = __half22float2(*(__half2*)&hv.z);
        sH[warp][f0 + 4] = fmaxf(p.x * sA[f0 + 4] + sB[f0 + 4], 0.f);
        sH[warp][f0 + 5] = fmaxf(p.y * sA[f0 + 5] + sB[f0 + 5], 0.f);
        p = __half22float2(*(__half2*)&hv.w);
        sH[warp][f0 + 6] = fmaxf(p.x * sA[f0 + 6] + sB[f0 + 6], 0.f);
        sH[warp][f0 + 7] = fmaxf(p.y * sA[f0 + 7] + sB[f0 + 7], 0.f);
    }
    __syncwarp();

    float logit = -1e30f;
    if (lane < NCLS) {
        float acc = sb2[lane];
#pragma unroll 8
        for (int f = 0; f < DIM; f++) acc += sH[warp][f] * sW[f * NCLS + lane];
        logit = acc;
    }
    float m = logit;
#pragma unroll
    for (int off = 16; off; off >>= 1) m = fmaxf(m, __shfl_xor_sync(0xffffffffu, m, off));
    float e = (lane < NCLS) ? __expf(logit - m) : 0.f;
    float ssum = e;
#pragma unroll
    for (int off = 16; off; off >>= 1) ssum += __shfl_xor_sync(0xffffffffu, ssum, off);
    if (lane < NCLS) out[(size_t)node * NCLS + lane] = e / ssum;
}

// ==================== host =================================================
extern "C" void kernel_launch(void* const* d_in, const int* in_sizes, int n_in,
                              void* d_out, int out_size)
{
    const float* x    = (const float*)d_in[0];
    const void*  ei   = d_in[1];
    const float* linw = (const float*)d_in[2];
    const float* c1w  = (const float*)d_in[3];
    const float* c1b  = (const float*)d_in[4];
    const float* c2w  = (const float*)d_in[5];
    const float* c2b  = (const float*)d_in[6];
    const float* m1w  = (const float*)d_in[7];
    const float* m1b  = (const float*)d_in[8];
    const float* gam  = (const float*)d_in[9];
    const float* bet  = (const float*)d_in[10];
    const float* m2w  = (const float*)d_in[11];
    const float* m2b  = (const float*)d_in[12];
    float* out = (float*)d_out;

    int Dd = in_sizes[4];                 // 256
    int G  = in_sizes[2] / Dd;            // 1002
    int n  = in_sizes[0] / G;             // 50000
    int E  = in_sizes[1] / 2;             // 800000

    unsigned short *xh, *pA, *pB, *whi;
    cudaGetSymbolAddress((void**)&xh,  g_xh);
    cudaGetSymbolAddress((void**)&pA,  g_pA);
    cudaGetSymbolAddress((void**)&pB,  g_pB);
    cudaGetSymbolAddress((void**)&whi, g_whi);

    const int GEMM_SMEM = 2 * STG_SZ;   // 40960
    cudaFuncSetAttribute(k_pgemm, cudaFuncAttributeMaxDynamicSharedMemorySize, GEMM_SMEM);

    const int tpb = 256;
    dim3 wblk(32, 8);
    dim3 grd(2, (n + 127) / 128);
    long long xtot = (long long)n * (KPAD0 / 2);

    k_xhalf<<<(int)((xtot + tpb - 1) / tpb), tpb>>>(x, n, G, xh);
    k_wprep<<<dim3(KPAD0 / 32, 8), wblk>>>(linw, G,   KPAD0, whi + WOFF0);
    k_wprep<<<dim3(8, 8),          wblk>>>(c1w,  256, 256,   whi + WOFF1);
    k_pgemm<<<grd, 256, GEMM_SMEM>>>(xh, whi + WOFF0, nullptr, pA, n, KPAD0);
    k_wprep<<<dim3(8, 8),          wblk>>>(c2w,  256, 256,   whi + WOFF2);
    k_wprep<<<dim3(8, 8),          wblk>>>(m1w,  256, 256,   whi + WOFF3);

    int initN = (n > 2 * DIM) ? n : 2 * DIM;
    k_init<<<(initN + tpb - 1) / tpb, tpb>>>(ei, E, n);
    k_count<<<(E + tpb - 1) / tpb, tpb>>>(ei, E);
    k_scan<<<1, 1024>>>(n);
    k_fill<<<(E + tpb - 1) / tpb, tpb>>>(ei, E);

    k_pgemm<<<grd, 256, GEMM_SMEM>>>(pA, whi + WOFF1, nullptr, pB, n, 256);
    k_aggregate<<<(n + 7) / 8, 256>>>(pB, c1b, pA, n);
    k_pgemm<<<grd, 256, GEMM_SMEM>>>(pA, whi + WOFF2, nullptr, pB, n, 256);
    k_aggregate<<<(n + 7) / 8, 256>>>(pB, c2b, pA, n);
    k_pgemm<<<grd, 256, GEMM_SMEM>>>(pA, whi + WOFF3, m1b, pB, n, 256);
    k_bnreduce<<<256, DIM>>>(pB, n);
    k_final<<<(n + 7) / 8, 256>>>(pB, m2w, m2b, gam, bet, out, n);
}

// round 17
// speedup vs baseline: 1.4947x; 1.0578x over previous
#include <cuda_runtime.h>
#include <cuda_fp16.h>
#include <cstdint>

#define DIM   256
#define NCLS  20
#define MAXN  50000
#define MAXE  800000
#define BN_EPS 1e-5f
#define KPAD0 1024

// ==================== device scratch =======================================
__device__ int   g_cnt[MAXN];
__device__ int   g_rowptr[MAXN + 1];
__device__ int   g_cursor[MAXN];
__device__ int   g_adj[MAXE];
__device__ float g_dinv[MAXN];
__device__ float g_bnsum[2 * DIM];
__device__ int   g_is64;
// activations: SINGLE fp16 plane (fp32 accumulate in MMA keeps precision)
__device__ unsigned short g_xh[(size_t)MAXN * KPAD0];
__device__ unsigned short g_pA[(size_t)MAXN * DIM];
__device__ unsigned short g_pB[(size_t)MAXN * DIM];
// weights: single fp16 plane [N=256][Kpad]; lin (Kpad=1024) + 3 x (Kpad=256)
#define WOFF0 0
#define WOFF1 (256 * 1024)
#define WOFF2 (WOFF1 + 256 * 256)
#define WOFF3 (WOFF2 + 256 * 256)
#define WTOT  (WOFF3 + 256 * 256)
__device__ unsigned short g_whi[WTOT];

// ==================== PTX helpers (non-'a' only!) ==========================
__device__ __forceinline__ uint32_t smem_u32(const void* p) {
    uint32_t a;
    asm("{ .reg .u64 t; cvta.to.shared.u64 t, %1; cvt.u32.u64 %0, t; }" : "=r"(a) : "l"(p));
    return a;
}
#define LDSM_X4(r, addr) \
    asm volatile("ldmatrix.sync.aligned.m8n8.x4.shared.b16 {%0,%1,%2,%3}, [%4];" \
        : "=r"((r)[0]), "=r"((r)[1]), "=r"((r)[2]), "=r"((r)[3]) : "r"(addr))
#define MMA_F16(cv, a, b0v, b1v) \
    asm volatile("mma.sync.aligned.m16n8k16.row.col.f32.f16.f16.f32 " \
        "{%0,%1,%2,%3}, {%4,%5,%6,%7}, {%8,%9}, {%0,%1,%2,%3};" \
        : "+f"((cv)[0]), "+f"((cv)[1]), "+f"((cv)[2]), "+f"((cv)[3]) \
        : "r"((a)[0]), "r"((a)[1]), "r"((a)[2]), "r"((a)[3]), "r"(b0v), "r"(b1v))
#define CP_ASYNC16(dst, src) \
    asm volatile("cp.async.cg.shared.global [%0], [%1], 16;" :: "r"(dst), "l"(src))
#define CP_COMMIT() asm volatile("cp.async.commit_group;" ::: "memory")

__device__ __forceinline__ unsigned packh2(float v0, float v1) {
    __half2 h = __floats2half2_rn(v0, v1);
    return *(unsigned*)&h;
}

// ==================== x half: fp32 [M][K] -> fp16 [M][1024] ================
__global__ void k_xhalf(const float* __restrict__ x, int M, int K,
                        unsigned short* __restrict__ xh)
{
    long long i = (long long)blockIdx.x * blockDim.x + threadIdx.x;
    long long total = (long long)M * (KPAD0 / 2);
    if (i >= total) return;
    int row = (int)(i >> 9);
    int p   = (int)(i & 511);
    float2 v = make_float2(0.f, 0.f);
    if (2 * p + 1 < K) v = *(const float2*)(x + (size_t)row * K + 2 * p);
    else if (2 * p < K) v.x = x[(size_t)row * K + 2 * p];
    ((unsigned*)xh)[(size_t)row * 512 + p] = packh2(v.x, v.y);
}

// ==================== init / CSR build =====================================
__global__ void k_init(const void* eiv, int E, int n) {
    int i = blockIdx.x * blockDim.x + threadIdx.x;
    if (i < n) g_cnt[i] = 0;
    if (i < 2 * DIM) g_bnsum[i] = 0.f;
    if (i == 0) {
        const long long* p = (const long long*)eiv;
        int ok = 1;
        int m = E < 64 ? E : 64;
        for (int k = 0; k < m; k++) {
            long long v = p[k];
            if (v < 0 || v >= (long long)n) { ok = 0; break; }
        }
        g_is64 = ok;
    }
}
__global__ void k_count(const void* eiv, int E) {
    int e = blockIdx.x * blockDim.x + threadIdx.x;
    if (e >= E) return;
    int d;
    if (g_is64) d = (int)((const long long*)eiv)[(size_t)E + e];
    else        d = ((const int*)eiv)[(size_t)E + e];
    atomicAdd(&g_cnt[d], 1);
}
__global__ void k_scan(int n) {
    __shared__ int part[1024];
    int t = threadIdx.x;
    int chunk = (n + 1023) >> 10;
    int beg = t * chunk;
    int end = beg + chunk; if (end > n) end = n;
    int s = 0;
    for (int i = beg; i < end; i++) s += g_cnt[i];
    part[t] = s;
    __syncthreads();
    for (int off = 1; off < 1024; off <<= 1) {
        int v = 0;
        if (t >= off) v = part[t - off];
        __syncthreads();
        part[t] += v;
        __syncthreads();
    }
    int run = (t == 0) ? 0 : part[t - 1];
    for (int i = beg; i < end; i++) {
        int c = g_cnt[i];
        g_rowptr[i] = run;
        g_cursor[i] = run;
        g_dinv[i] = rsqrtf((float)c + 1.0f);
        run += c;
    }
    if (beg < n && end == n) g_rowptr[n] = run;
}
__global__ void k_fill(const void* eiv, int E) {
    int e = blockIdx.x * blockDim.x + threadIdx.x;
    if (e >= E) return;
    int s, d;
    if (g_is64) {
        const long long* p = (const long long*)eiv;
        s = (int)p[e]; d = (int)p[(size_t)E + e];
    } else {
        const int* p = (const int*)eiv;
        s = p[e]; d = p[(size_t)E + e];
    }
    int pos = atomicAdd(&g_cursor[d], 1);
    g_adj[pos] = s;
}

// ==================== weight prep: transpose + single fp16 plane ===========
__global__ void k_wprep(const float* __restrict__ w, int K, int Kpad,
                        unsigned short* __restrict__ hi)
{
    __shared__ float t[32][33];
    int k0 = blockIdx.x * 32, n0 = blockIdx.y * 32;
    int tx = threadIdx.x, ty = threadIdx.y;   // 32 x 8
#pragma unroll
    for (int r = 0; r < 4; r++) {
        int k = k0 + ty + r * 8;
        t[ty + r * 8][tx] = (k < K) ? w[(size_t)k * 256 + n0 + tx] : 0.f;
    }
    __syncthreads();
#pragma unroll
    for (int r = 0; r < 4; r++) {
        int nn = n0 + ty + r * 8;
        int k  = k0 + tx;
        hi[(size_t)nn * Kpad + k] = __half_as_ushort(__float2half_rn(t[tx][ty + r * 8]));
    }
}

// ==================== fp16 GEMM: C = A @ W^T (fp32 accumulate) =============
// A fp16 [M][Kpad]; B fp16 [256][Kpad]; C fp16 [M][256].
// CTA 128x128, 8 warps 4(M)x2(N), BK=32, 3-stage cp.async (wait_group 1
// steady state -> loads get 2 compute sections of slack), 1 barrier/iter.
#define SM_P 80
#define SM_A 0
#define SM_B 10240
#define STG_SZ 20480
__global__ __launch_bounds__(256, 2) void k_pgemm(
    const unsigned short* __restrict__ Ah,
    const unsigned short* __restrict__ Bh,
    const float* __restrict__ bias,
    unsigned short* __restrict__ Ch,
    int M, int Kpad)
{
    extern __shared__ __align__(16) unsigned char sm[];
    uint32_t sb = smem_u32(sm);
    int tid = threadIdx.x, wid = tid >> 5, lane = tid & 31;
    int row0 = blockIdx.y * 128;
    int c0   = blockIdx.x * 128;
    int wm = wid & 3, wn = wid >> 2;

    float cacc[2][8][4];
#pragma unroll
    for (int a = 0; a < 2; a++)
#pragma unroll
        for (int b = 0; b < 8; b++)
#pragma unroll
            for (int d = 0; d < 4; d++) cacc[a][b][d] = 0.f;

    // loader: 2 threads per row, 32B (16 halves) each
    int arow = tid >> 1;
    int half = tid & 1;
    bool aOK = (row0 + arow) < M;
    const unsigned short* AhB = Ah + (size_t)(row0 + arow) * Kpad + half * 16;
    const unsigned short* BhB = Bh + (size_t)(c0 + arow) * Kpad + half * 16;
    uint32_t sOff = (uint32_t)(arow * SM_P + half * 32);

    // ldmatrix lane addresses (R5-proven layout)
    uint32_t aOff = (uint32_t)((wm * 32 + (lane & 15)) * SM_P + (lane >> 4) * 16);
    uint32_t bOff = (uint32_t)((wn * 64 + (lane & 7) + ((lane >> 4) & 1) * 8) * SM_P
                               + ((lane >> 3) & 1) * 16);

#define ISSUE_STAGE(stg_, kb_) do { \
    if (aOK) { \
        CP_ASYNC16((stg_) + SM_A + sOff,      AhB + (kb_)); \
        CP_ASYNC16((stg_) + SM_A + sOff + 16, AhB + (kb_) + 8); \
    } \
    CP_ASYNC16((stg_) + SM_B + sOff,      BhB + (kb_)); \
    CP_ASYNC16((stg_) + SM_B + sOff + 16, BhB + (kb_) + 8); \
} while (0)

    int NB = Kpad >> 5;   // always >= 8
    // prologue: stages 0 and 1 in flight
    ISSUE_STAGE(sb, 0);
    CP_COMMIT();
    ISSUE_STAGE(sb + STG_SZ, 32);
    CP_COMMIT();

    for (int ib = 0; ib < NB; ib++) {
        uint32_t cur = sb + (uint32_t)(ib % 3) * STG_SZ;
        if (ib + 1 < NB) {
            asm volatile("cp.async.wait_group 1;" ::: "memory");  // cur done, newest may fly
        } else {
            asm volatile("cp.async.wait_group 0;" ::: "memory");
        }
        __syncthreads();   // all warps past iter ib-1 compute; cur visible
        if (ib + 2 < NB) {
            uint32_t nst = sb + (uint32_t)((ib + 2) % 3) * STG_SZ;
            ISSUE_STAGE(nst, (ib + 2) << 5);
            CP_COMMIT();   // overlaps compute of cur AND next
        }
        // ---- compute: 2 k-frags x 16 MMAs
#pragma unroll
        for (int kf = 0; kf < 2; kf++) {
            uint32_t a[2][4];
#pragma unroll
            for (int mf = 0; mf < 2; mf++) {
                uint32_t addr = cur + SM_A + aOff + (uint32_t)(mf * 16 * SM_P + kf * 32);
                LDSM_X4(a[mf], addr);
            }
#pragma unroll
            for (int nph = 0; nph < 2; nph++) {
                int np0 = nph * 2, np1 = nph * 2 + 1;
                uint32_t b0[4], b1[4];
                LDSM_X4(b0, cur + SM_B + bOff + (uint32_t)(np0 * 16 * SM_P + kf * 32));
                LDSM_X4(b1, cur + SM_B + bOff + (uint32_t)(np1 * 16 * SM_P + kf * 32));
                MMA_F16(cacc[0][np0 * 2],     a[0], b0[0], b0[1]);
                MMA_F16(cacc[1][np0 * 2],     a[1], b0[0], b0[1]);
                MMA_F16(cacc[0][np0 * 2 + 1], a[0], b0[2], b0[3]);
                MMA_F16(cacc[1][np0 * 2 + 1], a[1], b0[2], b0[3]);
                MMA_F16(cacc[0][np1 * 2],     a[0], b1[0], b1[1]);
                MMA_F16(cacc[1][np1 * 2],     a[1], b1[0], b1[1]);
                MMA_F16(cacc[0][np1 * 2 + 1], a[0], b1[2], b1[3]);
                MMA_F16(cacc[1][np1 * 2 + 1], a[1], b1[2], b1[3]);
            }
        }
    }
#undef ISSUE_STAGE

    // ---- epilogue: fp16 output
    int g = lane >> 2, tq = lane & 3;
#pragma unroll
    for (int mf = 0; mf < 2; mf++) {
        int r = row0 + wm * 32 + mf * 16 + g;
#pragma unroll
        for (int nf = 0; nf < 8; nf++) {
            int cc = c0 + wn * 64 + nf * 8 + tq * 2;
            float b0 = 0.f, b1 = 0.f;
            if (bias) { b0 = __ldg(bias + cc); b1 = __ldg(bias + cc + 1); }
            if (r < M)
                *(unsigned*)(Ch + (size_t)r * 256 + cc) =
                    packh2(cacc[mf][nf][0] + b0, cacc[mf][nf][1] + b1);
            if (r + 8 < M)
                *(unsigned*)(Ch + (size_t)(r + 8) * 256 + cc) =
                    packh2(cacc[mf][nf][2] + b0, cacc[mf][nf][3] + b1);
        }
    }
}

// ==================== GCN aggregation (warp per node, MLP=4 unroll) ========
__global__ void k_aggregate(const unsigned short* __restrict__ t,
                            const float* __restrict__ bias,
                            unsigned short* __restrict__ o, int n)
{
    int warp = (blockIdx.x * blockDim.x + threadIdx.x) >> 5;
    int lane = threadIdx.x & 31;
    if (warp >= n) return;
    int node = warp;
    float dd  = g_dinv[node];
    int beg = g_rowptr[node], end = g_rowptr[node + 1];
    float acc[8];
#pragma unroll
    for (int j = 0; j < 8; j++) acc[j] = 0.f;

    int j = beg;
    // 4-way batched gather: 4 independent row loads in flight per warp
    for (; j + 4 <= end; j += 4) {
        int s0 = g_adj[j], s1 = g_adj[j + 1], s2 = g_adj[j + 2], s3 = g_adj[j + 3];
        float d0 = g_dinv[s0], d1 = g_dinv[s1], d2 = g_dinv[s2], d3 = g_dinv[s3];
        uint4 r0 = *((const uint4*)(t + (size_t)s0 * DIM) + lane);
        uint4 r1 = *((const uint4*)(t + (size_t)s1 * DIM) + lane);
        uint4 r2 = *((const uint4*)(t + (size_t)s2 * DIM) + lane);
        uint4 r3 = *((const uint4*)(t + (size_t)s3 * DIM) + lane);
        float2 p;
        // accumulate in j order (bit-identical to serial loop)
        p = __half22float2(*(__half2*)&r0.x); acc[0] += d0 * p.x; acc[1] += d0 * p.y;
        p = __half22float2(*(__half2*)&r0.y); acc[2] += d0 * p.x; acc[3] += d0 * p.y;
        p = __half22float2(*(__half2*)&r0.z); acc[4] += d0 * p.x; acc[5] += d0 * p.y;
        p = __half22float2(*(__half2*)&r0.w); acc[6] += d0 * p.x; acc[7] += d0 * p.y;
        p = __half22float2(*(__half2*)&r1.x); acc[0] += d1 * p.x; acc[1] += d1 * p.y;
        p = __half22float2(*(__half2*)&r1.y); acc[2] += d1 * p.x; acc[3] += d1 * p.y;
        p = __half22float2(*(__half2*)&r1.z); acc[4] += d1 * p.x; acc[5] += d1 * p.y;
        p = __half22float2(*(__half2*)&r1.w); acc[6] += d1 * p.x; acc[7] += d1 * p.y;
        p = __half22float2(*(__half2*)&r2.x); acc[0] += d2 * p.x; acc[1] += d2 * p.y;
        p = __half22float2(*(__half2*)&r2.y); acc[2] += d2 * p.x; acc[3] += d2 * p.y;
        p = __half22float2(*(__half2*)&r2.z); acc[4] += d2 * p.x; acc[5] += d2 * p.y;
        p = __half22float2(*(__half2*)&r2.w); acc[6] += d2 * p.x; acc[7] += d2 * p.y;
        p = __half22float2(*(__half2*)&r3.x); acc[0] += d3 * p.x; acc[1] += d3 * p.y;
        p = __half22float2(*(__half2*)&r3.y); acc[2] += d3 * p.x; acc[3] += d3 * p.y;
        p = __half22float2(*(__half2*)&r3.z); acc[4] += d3 * p.x; acc[5] += d3 * p.y;
        p = __half22float2(*(__half2*)&r3.w); acc[6] += d3 * p.x; acc[7] += d3 * p.y;
    }
    for (; j < end; j++) {
        int s = g_adj[j];
        float ds = g_dinv[s];
        uint4 hv = *((const uint4*)(t + (size_t)s * DIM) + lane);
        float2 p;
        p = __half22float2(*(__half2*)&hv.x); acc[0] += ds * p.x; acc[1] += ds * p.y;
        p = __half22float2(*(__half2*)&hv.y); acc[2] += ds * p.x; acc[3] += ds * p.y;
        p = __half22float2(*(__half2*)&hv.z); acc[4] += ds * p.x; acc[5] += ds * p.y;
        p = __half22float2(*(__half2*)&hv.w); acc[6] += ds * p.x; acc[7] += ds * p.y;
    }

    uint4 shv = *((const uint4*)(t + (size_t)node * DIM) + lane);
    float4 b0 = ((const float4*)bias)[lane * 2];
    float4 b1 = ((const float4*)bias)[lane * 2 + 1];
    float dd2 = dd * dd;
    float v[8];
    float2 p;
    p = __half22float2(*(__half2*)&shv.x);
    v[0] = dd * acc[0] + dd2 * p.x + b0.x; v[1] = dd * acc[1] + dd2 * p.y + b0.y;
    p = __half22float2(*(__half2*)&shv.y);
    v[2] = dd * acc[2] + dd2 * p.x + b0.z; v[3] = dd * acc[3] + dd2 * p.y + b0.w;
    p = __half22float2(*(__half2*)&shv.z);
    v[4] = dd * acc[4] + dd2 * p.x + b1.x; v[5] = dd * acc[5] + dd2 * p.y + b1.y;
    p = __half22float2(*(__half2*)&shv.w);
    v[6] = dd * acc[6] + dd2 * p.x + b1.z; v[7] = dd * acc[7] + dd2 * p.y + b1.w;
#pragma unroll
    for (int jj = 0; jj < 8; jj++) v[jj] = fmaxf(v[jj], 0.f);
    uint4 ov;
    ov.x = packh2(v[0], v[1]);
    ov.y = packh2(v[2], v[3]);
    ov.z = packh2(v[4], v[5]);
    ov.w = packh2(v[6], v[7]);
    *((uint4*)(o + (size_t)node * DIM) + lane) = ov;
}

// ==================== BN stats + fused final (fp16 input) ==================
__global__ void k_bnreduce(const unsigned short* __restrict__ t, int n) {
    int f = threadIdx.x;
    float s = 0.f, q = 0.f;
    for (int r = blockIdx.x; r < n; r += gridDim.x) {
        float v = __half2float(__ushort_as_half(t[(size_t)r * DIM + f]));
        s += v; q += v * v;
    }
    atomicAdd(&g_bnsum[f], s);
    atomicAdd(&g_bnsum[DIM + f], q);
}

__global__ __launch_bounds__(256) void k_final(
    const unsigned short* __restrict__ t,
    const float* __restrict__ w2, const float* __restrict__ b2,
    const float* __restrict__ gamma, const float* __restrict__ beta,
    float* __restrict__ out, int n)
{
    __shared__ float sW[DIM * NCLS];
    __shared__ float sA[DIM], sB[DIM];
    __shared__ float sb2[NCLS];
    __shared__ float sH[8][DIM];
    int tid = threadIdx.x;
    for (int i = tid; i < DIM * NCLS; i += 256) sW[i] = w2[i];
    if (tid < NCLS) sb2[tid] = b2[tid];
    {
        float invn = 1.0f / (float)n;
        float mu  = g_bnsum[tid] * invn;
        float var = g_bnsum[DIM + tid] * invn - mu * mu;
        float rs  = rsqrtf(var + BN_EPS);
        float a   = rs * gamma[tid];
        sA[tid] = a;
        sB[tid] = beta[tid] - mu * a;
    }
    __syncthreads();

    int warp = tid >> 5, lane = tid & 31;
    int node = blockIdx.x * 8 + warp;
    if (node >= n) return;

    uint4 hv = *((const uint4*)(t + (size_t)node * DIM) + lane);
    int f0 = lane * 8;
    {
        float2 p;
        p = __half22float2(*(__half2*)&hv.x);
        sH[warp][f0 + 0] = fmaxf(p.x * sA[f0 + 0] + sB[f0 + 0], 0.f);
        sH[warp][f0 + 1] = fmaxf(p.y * sA[f0 + 1] + sB[f0 + 1], 0.f);
        p = __half22float2(*(__half2*)&hv.y);
        sH[warp][f0 + 2] = fmaxf(p.x * sA[f0 + 2] + sB[f0 + 2], 0.f);
        sH[warp][f0 + 3] = fmaxf(p.y * sA[f0 + 3] + sB[f0 + 3], 0.f);
        p = __half22float2(*(__half2*)&hv.z);
        sH[warp][f0 + 4] = fmaxf(p.x * sA[f0 + 4] + sB[f0 + 4], 0.f);
        sH[warp][f0 + 5] = fmaxf(p.y * sA[f0 + 5] + sB[f0 + 5], 0.f);
        p = __half22float2(*(__half2*)&hv.w);
        sH[warp][f0 + 6] = fmaxf(p.x * sA[f0 + 6] + sB[f0 + 6], 0.f);
        sH[warp][f0 + 7] = fmaxf(p.y * sA[f0 + 7] + sB[f0 + 7], 0.f);
    }
    __syncwarp();

    float logit = -1e30f;
    if (lane < NCLS) {
        float acc = sb2[lane];
#pragma unroll 8
        for (int f = 0; f < DIM; f++) acc += sH[warp][f] * sW[f * NCLS + lane];
        logit = acc;
    }
    float m = logit;
#pragma unroll
    for (int off = 16; off; off >>= 1) m = fmaxf(m, __shfl_xor_sync(0xffffffffu, m, off));
    float e = (lane < NCLS) ? __expf(logit - m) : 0.f;
    float ssum = e;
#pragma unroll
    for (int off = 16; off; off >>= 1) ssum += __shfl_xor_sync(0xffffffffu, ssum, off);
    if (lane < NCLS) out[(size_t)node * NCLS + lane] = e / ssum;
}

// ==================== host =================================================
extern "C" void kernel_launch(void* const* d_in, const int* in_sizes, int n_in,
                              void* d_out, int out_size)
{
    const float* x    = (const float*)d_in[0];
    const void*  ei   = d_in[1];
    const float* linw = (const float*)d_in[2];
    const float* c1w  = (const float*)d_in[3];
    const float* c1b  = (const float*)d_in[4];
    const float* c2w  = (const float*)d_in[5];
    const float* c2b  = (const float*)d_in[6];
    const float* m1w  = (const float*)d_in[7];
    const float* m1b  = (const float*)d_in[8];
    const float* gam  = (const float*)d_in[9];
    const float* bet  = (const float*)d_in[10];
    const float* m2w  = (const float*)d_in[11];
    const float* m2b  = (const float*)d_in[12];
    float* out = (float*)d_out;

    int Dd = in_sizes[4];                 // 256
    int G  = in_sizes[2] / Dd;            // 1002
    int n  = in_sizes[0] / G;             // 50000
    int E  = in_sizes[1] / 2;             // 800000

    unsigned short *xh, *pA, *pB, *whi;
    cudaGetSymbolAddress((void**)&xh,  g_xh);
    cudaGetSymbolAddress((void**)&pA,  g_pA);
    cudaGetSymbolAddress((void**)&pB,  g_pB);
    cudaGetSymbolAddress((void**)&whi, g_whi);

    const int GEMM_SMEM = 3 * STG_SZ;   // 61440
    cudaFuncSetAttribute(k_pgemm, cudaFuncAttributeMaxDynamicSharedMemorySize, GEMM_SMEM);

    const int tpb = 256;
    dim3 wblk(32, 8);
    dim3 grd(2, (n + 127) / 128);
    long long xtot = (long long)n * (KPAD0 / 2);

    k_xhalf<<<(int)((xtot + tpb - 1) / tpb), tpb>>>(x, n, G, xh);
    k_wprep<<<dim3(KPAD0 / 32, 8), wblk>>>(linw, G,   KPAD0, whi + WOFF0);
    k_wprep<<<dim3(8, 8),          wblk>>>(c1w,  256, 256,   whi + WOFF1);
    k_pgemm<<<grd, 256, GEMM_SMEM>>>(xh, whi + WOFF0, nullptr, pA, n, KPAD0);
    k_wprep<<<dim3(8, 8),          wblk>>>(c2w,  256, 256,   whi + WOFF2);
    k_wprep<<<dim3(8, 8),          wblk>>>(m1w,  256, 256,   whi + WOFF3);

    int initN = (n > 2 * DIM) ? n : 2 * DIM;
    k_init<<<(initN + tpb - 1) / tpb, tpb>>>(ei, E, n);
    k_count<<<(E + tpb - 1) / tpb, tpb>>>(ei, E);
    k_scan<<<1, 1024>>>(n);
    k_fill<<<(E + tpb - 1) / tpb, tpb>>>(ei, E);

    k_pgemm<<<grd, 256, GEMM_SMEM>>>(pA, whi + WOFF1, nullptr, pB, n, 256);
    k_aggregate<<<(n + 7) / 8, 256>>>(pB, c1b, pA, n);
    k_pgemm<<<grd, 256, GEMM_SMEM>>>(pA, whi + WOFF2, nullptr, pB, n, 256);
    k_aggregate<<<(n + 7) / 8, 256>>>(pB, c2b, pA, n);
    k_pgemm<<<grd, 256, GEMM_SMEM>>>(pA, whi + WOFF3, m1b, pB, n, 256);
    k_bnreduce<<<256, DIM>>>(pB, n);
    k_final<<<(n + 7) / 8, 256>>>(pB, m2w, m2b, gam, bet, out, n);
}